// round 1
// baseline (speedup 1.0000x reference)
#include <cuda_runtime.h>
#include <math.h>

// Problem constants
#define NQ       10
#define NSTATE   1024          // 2^10 amplitudes
#define NPAIRS   512
#define NIN      49
#define THREADS  128
#define NGATES   30            // 3 layers x 10 fused (RY_enc * RX_theta) gates

// Batch-independent precomputed data (written by prep kernel, read by circuit kernel)
__device__ float gEncA[NGATES];   // (pi/2) * softplus(alpha_raw)+1e-6   (half-angle coefficient on x)
__device__ float gEncB[NGATES];   // (pi/2) * tanh(beta_raw)
__device__ float gThC[NGATES];    // cos(theta/2)
__device__ float gThS[NGATES];    // sin(theta/2)
__device__ float gWz[NSTATE];     // per-basis-state Z-weight: sum_q w[q] * (1 - 2*bit(9-q))
__device__ float gScale;          // clipped logit scale
__device__ float gBias;           // head bias

__global__ void prep_kernel(const float* __restrict__ theta,
                            const float* __restrict__ alpha_raw,
                            const float* __restrict__ beta_raw,
                            const float* __restrict__ head_w,
                            const float* __restrict__ head_b,
                            const float* __restrict__ logit_scale) {
    int t = threadIdx.x;
    if (t < NGATES) {
        // feature index for gate g = (layer*10+q) % 49 = g  (g < 30 < 49)
        float a = alpha_raw[t];
        // numerically stable softplus: max(a,0) + log1p(exp(-|a|))
        float sp = fmaxf(a, 0.0f) + log1pf(expf(-fabsf(a)));
        float alpha = sp + 1e-6f;
        float beta  = tanhf(beta_raw[t]);           // ENC_BETA_MAX = 1.0
        const float HALF_PI = 1.5707963267948966f;  // 0.5 * ENC_LAMBDA
        gEncA[t] = HALF_PI * alpha;
        gEncB[t] = HALF_PI * beta;
        float h = 0.5f * theta[t];
        gThC[t] = cosf(h);
        gThS[t] = sinf(h);
    }
    if (t == 0) {
        gScale = fminf(fmaxf(logit_scale[0], 0.5f), 80.0f);
        gBias  = head_b[0];
    }
    if (t < NSTATE) {
        float w = 0.0f;
#pragma unroll
        for (int q = 0; q < NQ; q++) {
            float wq = head_w[q];
            w += ((t >> (NQ - 1 - q)) & 1) ? -wq : wq;   // qubit q <-> bit (9-q)
        }
        gWz[t] = w;
    }
}

// One block per sample. State (1024 complex64) double-buffered in shared memory.
// Per layer: 10 fused single-qubit gates (in place) + 1 CNOT-chain permutation
// pass (gather into the other buffer: new[y] = old[y ^ (y>>1)]).
__global__ void __launch_bounds__(THREADS)
circuit_kernel(const float* __restrict__ x, float* __restrict__ out, int batch) {
    __shared__ float2 bufA[NSTATE];
    __shared__ float2 bufB[NSTATE];
    __shared__ float cAx[NGATES], cAy[NGATES], cBx[NGATES], cBy[NGATES];
    __shared__ float warpsum[THREADS / 32];

    const int b   = blockIdx.x;
    const int tid = threadIdx.x;
    if (b >= batch) return;

    // ---- per-sample fused gate coefficients: U = RX(theta) * RY(enc) ----
    // A = cx*cy - i sx*sy,  B = cx*sy + i sx*cy ; U = [[A,-B],[conj(B),conj(A)]]
    if (tid < NGATES) {
        float xv = x[b * NIN + tid];           // feature index == gate index (g < 30)
        float hy = gEncA[tid] * xv + gEncB[tid];
        float sy, cy;
        sincosf(hy, &sy, &cy);
        float cx = gThC[tid], sx = gThS[tid];
        cAx[tid] = cx * cy;
        cAy[tid] = -sx * sy;
        cBx[tid] = cx * sy;
        cBy[tid] = sx * cy;
    }

    // ---- init |0...0> ----
#pragma unroll
    for (int k = 0; k < NSTATE / THREADS; k++)
        bufA[tid + k * THREADS] = make_float2(0.0f, 0.0f);
    __syncthreads();
    if (tid == 0) bufA[0] = make_float2(1.0f, 0.0f);
    __syncthreads();

    float2* cur = bufA;
    float2* nxt = bufB;

#pragma unroll
    for (int layer = 0; layer < 3; layer++) {
        // 10 fused single-qubit gates, qubit q acts on index bit (9-q)
#pragma unroll
        for (int q = 0; q < NQ; q++) {
            const int g    = layer * NQ + q;
            const int bit  = NQ - 1 - q;
            const int mask = 1 << bit;
            const float Ax = cAx[g], Ay = cAy[g], Bx = cBx[g], By = cBy[g];
#pragma unroll
            for (int k = 0; k < NPAIRS / THREADS; k++) {
                int p  = tid + k * THREADS;
                int lo = p & (mask - 1);
                int i0 = ((p ^ lo) << 1) | lo;
                int i1 = i0 | mask;
                float2 a = cur[i0], d = cur[i1];
                float2 n0, n1;
                // n0 = A*a - B*d
                n0.x = Ax * a.x - Ay * a.y - Bx * d.x + By * d.y;
                n0.y = Ax * a.y + Ay * a.x - Bx * d.y - By * d.x;
                // n1 = conj(B)*a + conj(A)*d
                n1.x = Bx * a.x + By * a.y + Ax * d.x + Ay * d.y;
                n1.y = Bx * a.y - By * a.x + Ax * d.y - Ay * d.x;
                cur[i0] = n0;
                cur[i1] = n1;
            }
            __syncthreads();
        }
        // CNOT chain (0->1->...->9) == permutation new[y] = old[y ^ (y>>1)]
#pragma unroll
        for (int k = 0; k < NSTATE / THREADS; k++) {
            int y  = tid + k * THREADS;
            nxt[y] = cur[y ^ (y >> 1)];
        }
        __syncthreads();
        float2* tmp = cur; cur = nxt; nxt = tmp;
    }

    // ---- readout: dot(|amp|^2, Wz), head, clip ----
    float acc = 0.0f;
#pragma unroll
    for (int k = 0; k < NSTATE / THREADS; k++) {
        int y    = tid + k * THREADS;
        float2 v = cur[y];
        acc = fmaf(v.x * v.x + v.y * v.y, gWz[y], acc);
    }
#pragma unroll
    for (int o = 16; o > 0; o >>= 1)
        acc += __shfl_down_sync(0xFFFFFFFFu, acc, o);
    if ((tid & 31) == 0) warpsum[tid >> 5] = acc;
    __syncthreads();
    if (tid == 0) {
        float r = (warpsum[0] + warpsum[1] + warpsum[2] + warpsum[3]) + gBias;
        r *= gScale;
        out[b] = fminf(fmaxf(r, -30.0f), 30.0f);
    }
}

extern "C" void kernel_launch(void* const* d_in, const int* in_sizes, int n_in,
                              void* d_out, int out_size) {
    const float* x           = (const float*)d_in[0];  // (B, 49)
    const float* theta       = (const float*)d_in[1];  // (30,)
    const float* alpha_raw   = (const float*)d_in[2];  // (49,)
    const float* beta_raw    = (const float*)d_in[3];  // (49,)
    const float* head_w      = (const float*)d_in[4];  // (1,10)
    const float* head_b      = (const float*)d_in[5];  // (1,)
    const float* logit_scale = (const float*)d_in[6];  // scalar
    float* out               = (float*)d_out;          // (B,1) float32

    int batch = in_sizes[0] / NIN;

    prep_kernel<<<1, NSTATE>>>(theta, alpha_raw, beta_raw, head_w, head_b, logit_scale);
    circuit_kernel<<<batch, THREADS>>>(x, out, batch);
}

// round 2
// speedup vs baseline: 1.6154x; 1.6154x over previous
#include <cuda_runtime.h>
#include <math.h>

#define NIN   49
#define WPB   4                 // warps (samples) per block
#define THREADS (32 * WPB)

// One warp simulates one sample's 10-qubit statevector entirely in registers.
// Amp index (10 bits): bits[9:5] = lane, bits[4:0] = register slot r.
// Qubit q acts on bit (9-q):  q<=4 -> lane bit (4-q),  q>=5 -> reg bit (9-q).
__global__ void __launch_bounds__(THREADS, 4)
qcirc_kernel(const float* __restrict__ x,
             const float* __restrict__ theta,
             const float* __restrict__ alpha_raw,
             const float* __restrict__ beta_raw,
             const float* __restrict__ head_w,
             const float* __restrict__ head_b,
             const float* __restrict__ logit_scale,
             float* __restrict__ out, int batch)
{
    const unsigned FULL = 0xFFFFFFFFu;
    const int lane = threadIdx.x & 31;
    const int warp = threadIdx.x >> 5;
    const int b    = blockIdx.x * WPB + warp;
    if (b >= batch) return;   // batch % WPB == 0 in practice; warps stay convergent

    // ---- per-lane fused gate coefficients: lane g owns gate g (g < 30) ----
    // U = RX(theta)*RY(enc) = [[A,-B],[conj(B),conj(A)]]
    // A = cx*cy - i*sx*sy,  B = cx*sy + i*sx*cy
    float myAx, myAy, myBx, myBy;
    {
        const int g  = (lane < 30) ? lane : 0;
        const float th = theta[g];
        const float ar = alpha_raw[g];
        const float br = beta_raw[g];
        const float xv = x[b * NIN + g];
        float sp    = fmaxf(ar, 0.0f) + log1pf(expf(-fabsf(ar)));   // softplus
        float alpha = sp + 1e-6f;
        float beta  = tanhf(br);
        const float HALF_PI = 1.5707963267948966f;                  // 0.5 * pi
        float hy = HALF_PI * (alpha * xv + beta);
        float sy, cy; sincosf(hy, &sy, &cy);
        float sx, cx; sincosf(0.5f * th, &sx, &cx);
        myAx = cx * cy;
        myAy = -sx * sy;
        myBx = cx * sy;
        myBy = sx * cy;
    }

    // ---- statevector |0...0> ----
    float sr[32], si[32];
#pragma unroll
    for (int r = 0; r < 32; r++) { sr[r] = 0.0f; si[r] = 0.0f; }
    if (lane == 0) sr[0] = 1.0f;

#pragma unroll 1
    for (int layer = 0; layer < 3; layer++) {
        const int gbase = layer * 10;

        // ---- qubits 0..4: lane-bit gates via shfl.xor butterfly ----
#pragma unroll
        for (int q = 0; q < 5; q++) {
            const int g  = gbase + q;
            const float Ax = __shfl_sync(FULL, myAx, g);
            const float Ay = __shfl_sync(FULL, myAy, g);
            const float Bx = __shfl_sync(FULL, myBx, g);
            const float By = __shfl_sync(FULL, myBy, g);
            const int m = 1 << (4 - q);
            const bool hi = (lane & m) != 0;
            // hi=0: new = A*own - B*p ; hi=1: new = conj(A)*own + conj(B)*p
            const float C1x = Ax;
            const float C1y = hi ? -Ay : Ay;
            const float C2x = hi ?  Bx : -Bx;
            const float C2y = -By;
#pragma unroll
            for (int r = 0; r < 32; r++) {
                const float pr = __shfl_xor_sync(FULL, sr[r], m);
                const float pi = __shfl_xor_sync(FULL, si[r], m);
                const float orr = sr[r], oii = si[r];
                sr[r] = C1x * orr - C1y * oii + C2x * pr - C2y * pi;
                si[r] = C1x * oii + C1y * orr + C2x * pi + C2y * pr;
            }
        }

        // ---- qubits 5..9: register-bit gates (pure FMA) ----
#pragma unroll
        for (int q = 5; q < 10; q++) {
            const int g  = gbase + q;
            const float Ax = __shfl_sync(FULL, myAx, g);
            const float Ay = __shfl_sync(FULL, myAy, g);
            const float Bx = __shfl_sync(FULL, myBx, g);
            const float By = __shfl_sync(FULL, myBy, g);
            const int bit = 9 - q;           // 4..0
            const int m   = 1 << bit;
#pragma unroll
            for (int k = 0; k < 16; k++) {
                const int lo = k & (m - 1);
                const int i0 = ((k ^ lo) << 1) | lo;
                const int i1 = i0 | m;
                const float ar_ = sr[i0], ai_ = si[i0];
                const float dr_ = sr[i1], di_ = si[i1];
                sr[i0] = Ax * ar_ - Ay * ai_ - Bx * dr_ + By * di_;
                si[i0] = Ax * ai_ + Ay * ar_ - Bx * di_ - By * dr_;
                sr[i1] = Bx * ar_ + By * ai_ + Ax * dr_ + Ay * di_;
                si[i1] = Bx * ai_ - By * ar_ + Ax * di_ - Ay * dr_;
            }
        }

        // ---- CNOT chain == gray permutation new[y] = old[y ^ (y>>1)] ----
        {
            const int srcLane = lane ^ (lane >> 1);
            const bool hi = (lane & 1) != 0;
            // step 1: lane gather, in place (reg j is warp-globally dead after its shfl)
#pragma unroll
            for (int j = 0; j < 32; j++) {
                sr[j] = __shfl_sync(FULL, sr[j], srcLane);
                si[j] = __shfl_sync(FULL, si[j], srcLane);
            }
            // step 2: compile-time gray renaming tr[r] = v[r^(r>>1)]
            float tr[32], ti[32];
#pragma unroll
            for (int r = 0; r < 32; r++) {
                const int gi = r ^ (r >> 1);
                tr[r] = sr[gi]; ti[r] = si[gi];
            }
            // step 3: lane-parity conditional swap of pairs (k, 31-k)
#pragma unroll
            for (int k = 0; k < 16; k++) {
                const float a_r = tr[k],      a_i = ti[k];
                const float b_r = tr[31 - k], b_i = ti[31 - k];
                sr[k]      = hi ? b_r : a_r;
                si[k]      = hi ? b_i : a_i;
                sr[31 - k] = hi ? a_r : b_r;
                si[31 - k] = hi ? a_i : b_i;
            }
        }
    }

    // ---- readout: sum_i |amp_i|^2 * Wz(i), head, clip ----
    const float w0 = head_w[0], w1 = head_w[1], w2 = head_w[2], w3 = head_w[3], w4 = head_w[4];
    const float w5 = head_w[5], w6 = head_w[6], w7 = head_w[7], w8 = head_w[8], w9 = head_w[9];
    // lane-dependent part: qubits 0..4 live in lane bits 4..0
    const float wl = (((lane >> 4) & 1) ? -w0 : w0)
                   + (((lane >> 3) & 1) ? -w1 : w1)
                   + (((lane >> 2) & 1) ? -w2 : w2)
                   + (((lane >> 1) & 1) ? -w3 : w3)
                   + ((lane & 1)        ? -w4 : w4);
    float u = 0.0f, v = 0.0f;
#pragma unroll
    for (int r = 0; r < 32; r++) {
        const float p = sr[r] * sr[r] + si[r] * si[r];
        // reg-dependent part: qubits 5..9 live in reg bits 4..0 (compile-time signs)
        const float wr = (((r >> 4) & 1) ? -w5 : w5)
                       + (((r >> 3) & 1) ? -w6 : w6)
                       + (((r >> 2) & 1) ? -w7 : w7)
                       + (((r >> 1) & 1) ? -w8 : w8)
                       + ((r & 1)        ? -w9 : w9);
        u += p;
        v = fmaf(p, wr, v);
    }
    float part = fmaf(wl, u, v);
#pragma unroll
    for (int o = 16; o > 0; o >>= 1)
        part += __shfl_xor_sync(FULL, part, o);

    if (lane == 0) {
        const float scale = fminf(fmaxf(logit_scale[0], 0.5f), 80.0f);
        float rr = scale * (part + head_b[0]);
        out[b] = fminf(fmaxf(rr, -30.0f), 30.0f);
    }
}

extern "C" void kernel_launch(void* const* d_in, const int* in_sizes, int n_in,
                              void* d_out, int out_size) {
    const float* x           = (const float*)d_in[0];  // (B, 49)
    const float* theta       = (const float*)d_in[1];  // (30,)
    const float* alpha_raw   = (const float*)d_in[2];  // (49,)
    const float* beta_raw    = (const float*)d_in[3];  // (49,)
    const float* head_w      = (const float*)d_in[4];  // (1,10)
    const float* head_b      = (const float*)d_in[5];  // (1,)
    const float* logit_scale = (const float*)d_in[6];  // scalar
    float* out               = (float*)d_out;          // (B,1) float32

    const int batch  = in_sizes[0] / NIN;
    const int blocks = (batch + WPB - 1) / WPB;
    qcirc_kernel<<<blocks, THREADS>>>(x, theta, alpha_raw, beta_raw,
                                      head_w, head_b, logit_scale, out, batch);
}

// round 3
// speedup vs baseline: 1.9765x; 1.2235x over previous
#include <cuda_runtime.h>
#include <math.h>

#define NIN 49

typedef unsigned long long u64;

// ---- f32x2 packed helpers (sm_100+) ----
__device__ __forceinline__ u64 pk2(float lo, float hi) {
    u64 r; asm("mov.b64 %0, {%1,%2};" : "=l"(r) : "f"(lo), "f"(hi)); return r;
}
__device__ __forceinline__ void upk2(float& lo, float& hi, u64 v) {
    asm("mov.b64 {%0,%1}, %2;" : "=f"(lo), "=f"(hi) : "l"(v));
}
__device__ __forceinline__ u64 fma2(u64 a, u64 b, u64 c) {
    u64 d; asm("fma.rn.f32x2 %0, %1, %2, %3;" : "=l"(d) : "l"(a), "l"(b), "l"(c)); return d;
}
__device__ __forceinline__ u64 mul2(u64 a, u64 b) {
    u64 d; asm("mul.rn.f32x2 %0, %1, %2;" : "=l"(d) : "l"(a), "l"(b)); return d;
}

// One warp = one sample. Amp index (10 bits): bits[9:5]=lane, bits[4:0]=reg slot.
// SoA packing over amp bit 0: srp[k] = (re[2k], re[2k+1]), sip[k] = (im[2k], im[2k+1]).
// Qubit q acts on bit (9-q): q<=4 -> lane bit (4-q); q in 5..8 -> packed reg bit (8-q);
// q==9 -> the packed (intra-register) bit, handled scalar.
__global__ void __launch_bounds__(32, 14)
qcirc_kernel(const float* __restrict__ x,
             const float* __restrict__ theta,
             const float* __restrict__ alpha_raw,
             const float* __restrict__ beta_raw,
             const float* __restrict__ head_w,
             const float* __restrict__ head_b,
             const float* __restrict__ logit_scale,
             float* __restrict__ out, int batch)
{
    const unsigned FULL = 0xFFFFFFFFu;
    const int lane = threadIdx.x & 31;
    const int b    = blockIdx.x;
    if (b >= batch) return;

    // ---- per-lane fused gate coefficients: lane g owns gate g (g < 30) ----
    // U = RX(theta)*RY(enc) = [[A,-B],[conj(B),conj(A)]]
    // A = cx*cy - i*sx*sy,  B = cx*sy + i*sx*cy
    float myAx, myAy, myBx, myBy;
    {
        const int g  = (lane < 30) ? lane : 0;
        const float th = theta[g];
        const float ar = alpha_raw[g];
        const float br = beta_raw[g];
        const float xv = x[b * NIN + g];
        float sp    = fmaxf(ar, 0.0f) + log1pf(expf(-fabsf(ar)));   // softplus
        float alpha = sp + 1e-6f;
        float beta  = tanhf(br);
        const float HALF_PI = 1.5707963267948966f;                  // 0.5 * pi
        float hy = HALF_PI * (alpha * xv + beta);
        float sy, cy; sincosf(hy, &sy, &cy);
        float sx, cx; sincosf(0.5f * th, &sx, &cx);
        myAx = cx * cy;
        myAy = -sx * sy;
        myBx = cx * sy;
        myBy = sx * cy;
    }

    // ---- statevector |0...0> (packed SoA) ----
    u64 srp[16], sip[16];
    const u64 zz = pk2(0.0f, 0.0f);
#pragma unroll
    for (int k = 0; k < 16; k++) { srp[k] = zz; sip[k] = zz; }
    if (lane == 0) srp[0] = pk2(1.0f, 0.0f);

#pragma unroll 1
    for (int layer = 0; layer < 3; layer++) {
        const int gbase = layer * 10;

        // ---- qubits 0..4: lane-bit gates via shfl.xor butterfly ----
#pragma unroll
        for (int q = 0; q < 5; q++) {
            const int g  = gbase + q;
            const float Ax = __shfl_sync(FULL, myAx, g);
            const float Ay = __shfl_sync(FULL, myAy, g);
            const float Bx = __shfl_sync(FULL, myBx, g);
            const float By = __shfl_sync(FULL, myBy, g);
            const int m = 1 << (4 - q);
            const bool hi = (lane & m) != 0;
            // hi=0: new = A*own - B*p ; hi=1: new = conj(A)*own + conj(B)*p
            const float C1x = Ax;
            const float C1y = hi ? -Ay : Ay;
            const float C2x = hi ?  Bx : -Bx;
            const float C2y = -By;
            const u64 c1x2  = pk2(C1x,  C1x);
            const u64 c1y2  = pk2(C1y,  C1y);
            const u64 nc1y2 = pk2(-C1y, -C1y);
            const u64 c2x2  = pk2(C2x,  C2x);
            const u64 c2y2  = pk2(C2y,  C2y);
            const u64 nc2y2 = pk2(-C2y, -C2y);
#pragma unroll
            for (int k = 0; k < 16; k++) {
                float r0, r1, i0, i1;
                upk2(r0, r1, srp[k]);
                upk2(i0, i1, sip[k]);
                const float pr0 = __shfl_xor_sync(FULL, r0, m);
                const float pr1 = __shfl_xor_sync(FULL, r1, m);
                const float pi0 = __shfl_xor_sync(FULL, i0, m);
                const float pi1 = __shfl_xor_sync(FULL, i1, m);
                const u64 prp = pk2(pr0, pr1);
                const u64 pip = pk2(pi0, pi1);
                // new_r = C1x*rp - C1y*ip + C2x*prp - C2y*pip
                u64 nr = mul2(c1x2, srp[k]);
                nr = fma2(nc1y2, sip[k], nr);
                nr = fma2(c2x2, prp, nr);
                nr = fma2(nc2y2, pip, nr);
                // new_i = C1x*ip + C1y*rp + C2x*pip + C2y*prp
                u64 ni = mul2(c1x2, sip[k]);
                ni = fma2(c1y2, srp[k], ni);
                ni = fma2(c2x2, pip, ni);
                ni = fma2(c2y2, prp, ni);
                srp[k] = nr; sip[k] = ni;
            }
        }

        // ---- qubits 5..8: packed-reg-bit gates (pure f32x2 FMA) ----
#pragma unroll
        for (int q = 5; q < 9; q++) {
            const int g  = gbase + q;
            const float Ax = __shfl_sync(FULL, myAx, g);
            const float Ay = __shfl_sync(FULL, myAy, g);
            const float Bx = __shfl_sync(FULL, myBx, g);
            const float By = __shfl_sync(FULL, myBy, g);
            const u64 ax2  = pk2(Ax,  Ax);
            const u64 ay2  = pk2(Ay,  Ay);
            const u64 nay2 = pk2(-Ay, -Ay);
            const u64 bx2  = pk2(Bx,  Bx);
            const u64 nbx2 = pk2(-Bx, -Bx);
            const u64 by2  = pk2(By,  By);
            const u64 nby2 = pk2(-By, -By);
            const int pm = 1 << (8 - q);          // packed-index bit
#pragma unroll
            for (int kk = 0; kk < 8; kk++) {
                const int lo = kk & (pm - 1);
                const int p0 = ((kk ^ lo) << 1) | lo;
                const int p1 = p0 | pm;
                const u64 ar = srp[p0], ai = sip[p0];
                const u64 dr = srp[p1], di = sip[p1];
                // n0 = A*a - B*d ; n1 = conj(B)*a + conj(A)*d
                u64 n0r = mul2(ax2, ar);
                n0r = fma2(nay2, ai, n0r); n0r = fma2(nbx2, dr, n0r); n0r = fma2(by2,  di, n0r);
                u64 n0i = mul2(ax2, ai);
                n0i = fma2(ay2,  ar, n0i); n0i = fma2(nbx2, di, n0i); n0i = fma2(nby2, dr, n0i);
                u64 n1r = mul2(bx2, ar);
                n1r = fma2(by2,  ai, n1r); n1r = fma2(ax2,  dr, n1r); n1r = fma2(ay2,  di, n1r);
                u64 n1i = mul2(bx2, ai);
                n1i = fma2(nby2, ar, n1i); n1i = fma2(ax2,  di, n1i); n1i = fma2(nay2, dr, n1i);
                srp[p0] = n0r; sip[p0] = n0i;
                srp[p1] = n1r; sip[p1] = n1i;
            }
        }

        // ---- qubit 9: intra-register (packed) bit, scalar ----
        {
            const int g  = gbase + 9;
            const float Ax = __shfl_sync(FULL, myAx, g);
            const float Ay = __shfl_sync(FULL, myAy, g);
            const float Bx = __shfl_sync(FULL, myBx, g);
            const float By = __shfl_sync(FULL, myBy, g);
#pragma unroll
            for (int k = 0; k < 16; k++) {
                float ar, dr, ai, di;
                upk2(ar, dr, srp[k]);
                upk2(ai, di, sip[k]);
                const float n0r = Ax*ar - Ay*ai - Bx*dr + By*di;
                const float n0i = Ax*ai + Ay*ar - Bx*di - By*dr;
                const float n1r = Bx*ar + By*ai + Ax*dr + Ay*di;
                const float n1i = Bx*ai - By*ar + Ax*di - Ay*dr;
                srp[k] = pk2(n0r, n1r);
                sip[k] = pk2(n0i, n1i);
            }
        }

        // ---- CNOT chain == gray permutation new[y] = old[y ^ (y>>1)] ----
        {
            float vr[32], vi[32];
#pragma unroll
            for (int k = 0; k < 16; k++) {
                upk2(vr[2*k], vr[2*k+1], srp[k]);
                upk2(vi[2*k], vi[2*k+1], sip[k]);
            }
            const int srcLane = lane ^ (lane >> 1);
            const bool hi = (lane & 1) != 0;
#pragma unroll
            for (int j = 0; j < 32; j++) {
                vr[j] = __shfl_sync(FULL, vr[j], srcLane);
                vi[j] = __shfl_sync(FULL, vi[j], srcLane);
            }
#pragma unroll
            for (int k = 0; k < 16; k++) {
                const int r0 = 2*k,  r1 = 2*k + 1;
                const int g00 = r0 ^ (r0 >> 1);
                const int g10 = (31 - r0) ^ ((31 - r0) >> 1);
                const int g01 = r1 ^ (r1 >> 1);
                const int g11 = (31 - r1) ^ ((31 - r1) >> 1);
                const float f0r = hi ? vr[g10] : vr[g00];
                const float f0i = hi ? vi[g10] : vi[g00];
                const float f1r = hi ? vr[g11] : vr[g01];
                const float f1i = hi ? vi[g11] : vi[g01];
                srp[k] = pk2(f0r, f1r);
                sip[k] = pk2(f0i, f1i);
            }
        }
    }

    // ---- readout: sum_i |amp_i|^2 * Wz(i), head, clip ----
    const float w0 = head_w[0], w1 = head_w[1], w2 = head_w[2], w3 = head_w[3], w4 = head_w[4];
    const float w5 = head_w[5], w6 = head_w[6], w7 = head_w[7], w8 = head_w[8], w9 = head_w[9];
    // lane-dependent part: qubits 0..4 live in lane bits 4..0
    const float wl = (((lane >> 4) & 1) ? -w0 : w0)
                   + (((lane >> 3) & 1) ? -w1 : w1)
                   + (((lane >> 2) & 1) ? -w2 : w2)
                   + (((lane >> 1) & 1) ? -w3 : w3)
                   + ((lane & 1)        ? -w4 : w4);
    float u = 0.0f, v = 0.0f;
#pragma unroll
    for (int k = 0; k < 16; k++) {
        float r0, r1, i0, i1;
        upk2(r0, r1, srp[k]);
        upk2(i0, i1, sip[k]);
        const float p0 = r0*r0 + i0*i0;
        const float p1 = r1*r1 + i1*i1;
        const int a0 = 2*k, a1 = 2*k + 1;
        const float wr0 = (((a0 >> 4) & 1) ? -w5 : w5)
                        + (((a0 >> 3) & 1) ? -w6 : w6)
                        + (((a0 >> 2) & 1) ? -w7 : w7)
                        + (((a0 >> 1) & 1) ? -w8 : w8)
                        + ((a0 & 1)        ? -w9 : w9);
        const float wr1 = (((a1 >> 4) & 1) ? -w5 : w5)
                        + (((a1 >> 3) & 1) ? -w6 : w6)
                        + (((a1 >> 2) & 1) ? -w7 : w7)
                        + (((a1 >> 1) & 1) ? -w8 : w8)
                        + ((a1 & 1)        ? -w9 : w9);
        u += p0 + p1;
        v = fmaf(p0, wr0, v);
        v = fmaf(p1, wr1, v);
    }
    float part = fmaf(wl, u, v);
#pragma unroll
    for (int o = 16; o > 0; o >>= 1)
        part += __shfl_xor_sync(FULL, part, o);

    if (lane == 0) {
        const float scale = fminf(fmaxf(logit_scale[0], 0.5f), 80.0f);
        float rr = scale * (part + head_b[0]);
        out[b] = fminf(fmaxf(rr, -30.0f), 30.0f);
    }
}

extern "C" void kernel_launch(void* const* d_in, const int* in_sizes, int n_in,
                              void* d_out, int out_size) {
    const float* x           = (const float*)d_in[0];  // (B, 49)
    const float* theta       = (const float*)d_in[1];  // (30,)
    const float* alpha_raw   = (const float*)d_in[2];  // (49,)
    const float* beta_raw    = (const float*)d_in[3];  // (49,)
    const float* head_w      = (const float*)d_in[4];  // (1,10)
    const float* head_b      = (const float*)d_in[5];  // (1,)
    const float* logit_scale = (const float*)d_in[6];  // scalar
    float* out               = (float*)d_out;          // (B,1) float32

    const int batch = in_sizes[0] / NIN;
    qcirc_kernel<<<batch, 32>>>(x, theta, alpha_raw, beta_raw,
                                head_w, head_b, logit_scale, out, batch);
}

// round 6
// speedup vs baseline: 2.4852x; 1.2574x over previous
#include <cuda_runtime.h>
#include <math.h>

#define NIN 49

typedef unsigned long long u64;

// ---- f32x2 packed helpers (sm_100+) ----
__device__ __forceinline__ u64 pk2(float lo, float hi) {
    u64 r; asm("mov.b64 %0, {%1,%2};" : "=l"(r) : "f"(lo), "f"(hi)); return r;
}
__device__ __forceinline__ void upk2(float& lo, float& hi, u64 v) {
    asm("mov.b64 {%0,%1}, %2;" : "=f"(lo), "=f"(hi) : "l"(v));
}
__device__ __forceinline__ u64 fma2(u64 a, u64 b, u64 c) {
    u64 d; asm("fma.rn.f32x2 %0, %1, %2, %3;" : "=l"(d) : "l"(a), "l"(b), "l"(c)); return d;
}
__device__ __forceinline__ u64 mul2(u64 a, u64 b) {
    u64 d; asm("mul.rn.f32x2 %0, %1, %2;" : "=l"(d) : "l"(a), "l"(b)); return d;
}

// c-index of amp a after folding the first gray permutation (compile-time)
__device__ __forceinline__ constexpr int cidx(int a) {
    return (((a >> 4) & 1) << 4)
         | ((((a >> 3) ^ (a >> 4)) & 1) << 3)
         | ((((a >> 2) ^ (a >> 3)) & 1) << 2)
         | ((((a >> 1) ^ (a >> 2)) & 1) << 1)
         | (((a ^ (a >> 1)) & 1));
}

// One warp = one sample. Amp index (10 bits): bits[9:5]=lane, bits[4:0]=reg slot.
// SoA packing over amp bit 0: srp[k] = (re[2k], re[2k+1]), sip[k] = (im[2k], im[2k+1]).
// Qubit q acts on bit (9-q): q<=4 -> lane bit (4-q); q in 5..8 -> packed reg bit (8-q);
// q==9 -> the packed (intra-register) bit, handled scalar.
// Layer 0 (product state) is constructed directly with its CNOT permutation folded in.
// The LAST layer's CNOT-chain permutation is folded into the readout weights.
__global__ void __launch_bounds__(32)
qcirc_kernel(const float* __restrict__ x,
             const float* __restrict__ theta,
             const float* __restrict__ alpha_raw,
             const float* __restrict__ beta_raw,
             const float* __restrict__ head_w,
             const float* __restrict__ head_b,
             const float* __restrict__ logit_scale,
             float* __restrict__ out, int batch)
{
    const unsigned FULL = 0xFFFFFFFFu;
    const int lane = threadIdx.x & 31;
    const int b    = blockIdx.x;
    if (b >= batch) return;

    // ---- per-lane fused gate coefficients: lane g owns gate g (g < 30) ----
    // U = RX(theta)*RY(enc) = [[A,-B],[conj(B),conj(A)]]
    // A = cx*cy - i*sx*sy,  B = cx*sy + i*sx*cy
    float myAx, myAy, myBx, myBy;
    {
        const int g  = (lane < 30) ? lane : 0;
        const float th = theta[g];
        const float ar = alpha_raw[g];
        const float br = beta_raw[g];
        const float xv = x[b * NIN + g];
        float sp    = fmaxf(ar, 0.0f) + log1pf(expf(-fabsf(ar)));   // softplus
        float alpha = sp + 1e-6f;
        float beta  = tanhf(br);
        const float HALF_PI = 1.5707963267948966f;                  // 0.5 * pi
        float hy = HALF_PI * (alpha * xv + beta);
        float sy, cy; sincosf(hy, &sy, &cy);
        float sx, cx; sincosf(0.5f * th, &sx, &cx);
        myAx = cx * cy;
        myAy = -sx * sy;
        myBx = cx * sy;
        myBy = sx * cy;
    }

    const int l4 = (lane >> 4) & 1, l3 = (lane >> 3) & 1, l2 = (lane >> 2) & 1,
              l1 = (lane >> 1) & 1, l0 = lane & 1;

    // =====================================================================
    // Layer 0 + its CNOT chain, folded: amp[y] = prod_q f_q(bit_{9-q}(y^(y>>1)))
    // f_q(0) = A_q = (Ax,Ay);  f_q(1) = conj(B_q) = (Bx,-By)
    // y' lane bits: q0<-l4, q1<-l3^l4, q2<-l2^l3, q3<-l1^l2, q4<-l0^l1 (lane-local)
    // y' reg bits:  q5<-a4^l0 (l0 folded into factor swap), q6<-a3^a4, q7<-a2^a3,
    //               q8<-a1^a2, q9<-a0^a1 (compile-time c-index renaming)
    // =====================================================================
    u64 srp[16], sip[16];
    {
        // lane factor (qubits 0..4)
        float lfr, lfi;
        {
            const int gb[5] = { l4, l3 ^ l4, l2 ^ l3, l1 ^ l2, l0 ^ l1 };
            float Ax = __shfl_sync(FULL, myAx, 0);
            float Ay = __shfl_sync(FULL, myAy, 0);
            float Bx = __shfl_sync(FULL, myBx, 0);
            float By = __shfl_sync(FULL, myBy, 0);
            lfr = gb[0] ? Bx : Ax;
            lfi = gb[0] ? -By : Ay;
#pragma unroll
            for (int q = 1; q < 5; q++) {
                Ax = __shfl_sync(FULL, myAx, q);
                Ay = __shfl_sync(FULL, myAy, q);
                Bx = __shfl_sync(FULL, myBx, q);
                By = __shfl_sync(FULL, myBy, q);
                const float fr = gb[q] ? Bx : Ax;
                const float fi = gb[q] ? -By : Ay;
                const float nr = lfr * fr - lfi * fi;
                const float ni = lfr * fi + lfi * fr;
                lfr = nr; lfi = ni;
            }
        }

        // reg-qubit factor pairs (qubits 5..9), j = q-5; qubit 5 gets l0-swap
        float f0r[5], f0i[5], f1r[5], f1i[5];
#pragma unroll
        for (int j = 0; j < 5; j++) {
            const int q = 5 + j;
            const float Ax = __shfl_sync(FULL, myAx, q);
            const float Ay = __shfl_sync(FULL, myAy, q);
            const float Bx = __shfl_sync(FULL, myBx, q);
            const float By = __shfl_sync(FULL, myBy, q);
            if (j == 0) {   // f5'(v) = f5(v ^ l0)
                f0r[j] = l0 ? Bx : Ax;  f0i[j] = l0 ? -By : Ay;
                f1r[j] = l0 ? Ax : Bx;  f1i[j] = l0 ? Ay : -By;
            } else {
                f0r[j] = Ax;  f0i[j] = Ay;
                f1r[j] = Bx;  f1i[j] = -By;
            }
        }

        // doubling tree over c-index (bit4<->q5 .. bit0<->q9), seeded with lane factor
        float gr[32], gi[32];
        gr[0] = lfr; gi[0] = lfi;
#pragma unroll
        for (int p = 0; p < 5; p++) {           // bit position p, qubit j = 4-p
            const int j  = 4 - p;
            const int sz = 1 << p;
#pragma unroll
            for (int c = 0; c < 32; c++) {       // only c < sz entries are live
                if (c < sz) {
                    const float orr = gr[c], oii = gi[c];
                    gr[c + sz] = orr * f1r[j] - oii * f1i[j];
                    gi[c + sz] = orr * f1i[j] + oii * f1r[j];
                    gr[c]      = orr * f0r[j] - oii * f0i[j];
                    gi[c]      = orr * f0i[j] + oii * f0r[j];
                }
            }
        }

        // pack into SoA state with compile-time c-index renaming
#pragma unroll
        for (int k = 0; k < 16; k++) {
            srp[k] = pk2(gr[cidx(2 * k)], gr[cidx(2 * k + 1)]);
            sip[k] = pk2(gi[cidx(2 * k)], gi[cidx(2 * k + 1)]);
        }
    }

    // =====================================================================
    // Layers 1 and 2
    // =====================================================================
#pragma unroll 1
    for (int layer = 1; layer < 3; layer++) {
        const int gbase = layer * 10;

        // ---- qubits 0..4: lane-bit gates via shfl.xor butterfly ----
#pragma unroll
        for (int q = 0; q < 5; q++) {
            const int g  = gbase + q;
            const float Ax = __shfl_sync(FULL, myAx, g);
            const float Ay = __shfl_sync(FULL, myAy, g);
            const float Bx = __shfl_sync(FULL, myBx, g);
            const float By = __shfl_sync(FULL, myBy, g);
            const int m = 1 << (4 - q);
            const bool hi = (lane & m) != 0;
            // hi=0: new = A*own - B*p ; hi=1: new = conj(A)*own + conj(B)*p
            const float C1x = Ax;
            const float C1y = hi ? -Ay : Ay;
            const float C2x = hi ?  Bx : -Bx;
            const float C2y = -By;
            const u64 c1x2  = pk2(C1x,  C1x);
            const u64 c1y2  = pk2(C1y,  C1y);
            const u64 nc1y2 = pk2(-C1y, -C1y);
            const u64 c2x2  = pk2(C2x,  C2x);
            const u64 c2y2  = pk2(C2y,  C2y);
            const u64 nc2y2 = pk2(-C2y, -C2y);
#pragma unroll
            for (int k = 0; k < 16; k++) {
                float r0, r1, i0, i1;
                upk2(r0, r1, srp[k]);
                upk2(i0, i1, sip[k]);
                const float pr0 = __shfl_xor_sync(FULL, r0, m);
                const float pr1 = __shfl_xor_sync(FULL, r1, m);
                const float pi0 = __shfl_xor_sync(FULL, i0, m);
                const float pi1 = __shfl_xor_sync(FULL, i1, m);
                const u64 prp = pk2(pr0, pr1);
                const u64 pip = pk2(pi0, pi1);
                // new_r = C1x*rp - C1y*ip + C2x*prp - C2y*pip
                u64 nr = mul2(c1x2, srp[k]);
                nr = fma2(nc1y2, sip[k], nr);
                nr = fma2(c2x2, prp, nr);
                nr = fma2(nc2y2, pip, nr);
                // new_i = C1x*ip + C1y*rp + C2x*pip + C2y*prp
                u64 ni = mul2(c1x2, sip[k]);
                ni = fma2(c1y2, srp[k], ni);
                ni = fma2(c2x2, pip, ni);
                ni = fma2(c2y2, prp, ni);
                srp[k] = nr; sip[k] = ni;
            }
        }

        // ---- qubits 5..8: packed-reg-bit gates (pure f32x2 FMA) ----
#pragma unroll
        for (int q = 5; q < 9; q++) {
            const int g  = gbase + q;
            const float Ax = __shfl_sync(FULL, myAx, g);
            const float Ay = __shfl_sync(FULL, myAy, g);
            const float Bx = __shfl_sync(FULL, myBx, g);
            const float By = __shfl_sync(FULL, myBy, g);
            const u64 ax2  = pk2(Ax,  Ax);
            const u64 ay2  = pk2(Ay,  Ay);
            const u64 nay2 = pk2(-Ay, -Ay);
            const u64 bx2  = pk2(Bx,  Bx);
            const u64 nbx2 = pk2(-Bx, -Bx);
            const u64 by2  = pk2(By,  By);
            const u64 nby2 = pk2(-By, -By);
            const int pm = 1 << (8 - q);          // packed-index bit
#pragma unroll
            for (int kk = 0; kk < 8; kk++) {
                const int lo = kk & (pm - 1);
                const int p0 = ((kk ^ lo) << 1) | lo;
                const int p1 = p0 | pm;
                const u64 ar = srp[p0], ai = sip[p0];
                const u64 dr = srp[p1], di = sip[p1];
                // n0 = A*a - B*d ; n1 = conj(B)*a + conj(A)*d
                u64 n0r = mul2(ax2, ar);
                n0r = fma2(nay2, ai, n0r); n0r = fma2(nbx2, dr, n0r); n0r = fma2(by2,  di, n0r);
                u64 n0i = mul2(ax2, ai);
                n0i = fma2(ay2,  ar, n0i); n0i = fma2(nbx2, di, n0i); n0i = fma2(nby2, dr, n0i);
                u64 n1r = mul2(bx2, ar);
                n1r = fma2(by2,  ai, n1r); n1r = fma2(ax2,  dr, n1r); n1r = fma2(ay2,  di, n1r);
                u64 n1i = mul2(bx2, ai);
                n1i = fma2(nby2, ar, n1i); n1i = fma2(ax2,  di, n1i); n1i = fma2(nay2, dr, n1i);
                srp[p0] = n0r; sip[p0] = n0i;
                srp[p1] = n1r; sip[p1] = n1i;
            }
        }

        // ---- qubit 9: intra-register (packed) bit, scalar ----
        {
            const int g  = gbase + 9;
            const float Ax = __shfl_sync(FULL, myAx, g);
            const float Ay = __shfl_sync(FULL, myAy, g);
            const float Bx = __shfl_sync(FULL, myBx, g);
            const float By = __shfl_sync(FULL, myBy, g);
#pragma unroll
            for (int k = 0; k < 16; k++) {
                float ar, dr, ai, di;
                upk2(ar, dr, srp[k]);
                upk2(ai, di, sip[k]);
                const float n0r = Ax*ar - Ay*ai - Bx*dr + By*di;
                const float n0i = Ax*ai + Ay*ar - Bx*di - By*dr;
                const float n1r = Bx*ar + By*ai + Ax*dr + Ay*di;
                const float n1i = Bx*ai - By*ar + Ax*di - Ay*dr;
                srp[k] = pk2(n0r, n1r);
                sip[k] = pk2(n0i, n1i);
            }
        }

        // ---- CNOT chain == gray permutation new[y] = old[y ^ (y>>1)] ----
        // (after layer 1 only; layer 2's permutation is folded into readout)
        if (layer < 2) {
            float vr[32], vi[32];
#pragma unroll
            for (int k = 0; k < 16; k++) {
                upk2(vr[2*k], vr[2*k+1], srp[k]);
                upk2(vi[2*k], vi[2*k+1], sip[k]);
            }
            const int srcLane = lane ^ (lane >> 1);
            const bool hi = (lane & 1) != 0;
#pragma unroll
            for (int j = 0; j < 32; j++) {
                vr[j] = __shfl_sync(FULL, vr[j], srcLane);
                vi[j] = __shfl_sync(FULL, vi[j], srcLane);
            }
#pragma unroll
            for (int k = 0; k < 16; k++) {
                const int r0 = 2*k,  r1 = 2*k + 1;
                const int g00 = r0 ^ (r0 >> 1);
                const int g10 = (31 - r0) ^ ((31 - r0) >> 1);
                const int g01 = r1 ^ (r1 >> 1);
                const int g11 = (31 - r1) ^ ((31 - r1) >> 1);
                const float f0r = hi ? vr[g10] : vr[g00];
                const float f0i = hi ? vi[g10] : vi[g00];
                const float f1r = hi ? vr[g11] : vr[g01];
                const float f1i = hi ? vi[g11] : vi[g01];
                srp[k] = pk2(f0r, f1r);
                sip[k] = pk2(f0i, f1i);
            }
        }
    }

    // ---- readout with folded final permutation ----
    // final[y] = S[y ^ (y>>1)]  =>  sum_y |final[y]|^2 Wz(y) = sum_z |S[z]|^2 Wz(Y(z)),
    // where Y_j = z_9 ^ ... ^ z_j (suffix XOR). Qubit q reads bit (9-q) of Y.
    const float w0 = head_w[0], w1 = head_w[1], w2 = head_w[2], w3 = head_w[3], w4 = head_w[4];
    const float w5 = head_w[5], w6 = head_w[6], w7 = head_w[7], w8 = head_w[8], w9 = head_w[9];
    const int c0 = l4, c1 = c0 ^ l3, c2 = c1 ^ l2, c3 = c2 ^ l1, c4 = c3 ^ l0;
    const float wl = (c0 ? -w0 : w0) + (c1 ? -w1 : w1) + (c2 ? -w2 : w2)
                   + (c3 ? -w3 : w3) + (c4 ? -w4 : w4);
    const int Plane = c4;   // parity of all lane bits; flips qubit-5..9 signs globally

    float u = 0.0f, v = 0.0f;
#pragma unroll
    for (int k = 0; k < 16; k++) {
        float r0, r1, i0, i1;
        upk2(r0, r1, srp[k]);
        upk2(i0, i1, sip[k]);
        const float p0 = r0*r0 + i0*i0;
        const float p1 = r1*r1 + i1*i1;
        const int a0 = 2*k, a1 = 2*k + 1;
        // suffix parities of the 5 reg bits, compile-time per amp
        const int t4_0 = (a0 >> 4) & 1,           t3_0 = t4_0 ^ ((a0 >> 3) & 1),
                  t2_0 = t3_0 ^ ((a0 >> 2) & 1),  t1_0 = t2_0 ^ ((a0 >> 1) & 1),
                  t0_0 = t1_0 ^ (a0 & 1);
        const int t4_1 = (a1 >> 4) & 1,           t3_1 = t4_1 ^ ((a1 >> 3) & 1),
                  t2_1 = t3_1 ^ ((a1 >> 2) & 1),  t1_1 = t2_1 ^ ((a1 >> 1) & 1),
                  t0_1 = t1_1 ^ (a1 & 1);
        const float wr0 = (t4_0 ? -w5 : w5) + (t3_0 ? -w6 : w6) + (t2_0 ? -w7 : w7)
                        + (t1_0 ? -w8 : w8) + (t0_0 ? -w9 : w9);
        const float wr1 = (t4_1 ? -w5 : w5) + (t3_1 ? -w6 : w6) + (t2_1 ? -w7 : w7)
                        + (t1_1 ? -w8 : w8) + (t0_1 ? -w9 : w9);
        u += p0 + p1;
        v = fmaf(p0, wr0, v);
        v = fmaf(p1, wr1, v);
    }
    float part = fmaf(wl, u, Plane ? -v : v);
#pragma unroll
    for (int o = 16; o > 0; o >>= 1)
        part += __shfl_xor_sync(FULL, part, o);

    if (lane == 0) {
        const float scale = fminf(fmaxf(logit_scale[0], 0.5f), 80.0f);
        float rr = scale * (part + head_b[0]);
        out[b] = fminf(fmaxf(rr, -30.0f), 30.0f);
    }
}

extern "C" void kernel_launch(void* const* d_in, const int* in_sizes, int n_in,
                              void* d_out, int out_size) {
    const float* x           = (const float*)d_in[0];  // (B, 49)
    const float* theta       = (const float*)d_in[1];  // (30,)
    const float* alpha_raw   = (const float*)d_in[2];  // (49,)
    const float* beta_raw    = (const float*)d_in[3];  // (49,)
    const float* head_w      = (const float*)d_in[4];  // (1,10)
    const float* head_b      = (const float*)d_in[5];  // (1,)
    const float* logit_scale = (const float*)d_in[6];  // scalar
    float* out               = (float*)d_out;          // (B,1) float32

    const int batch = in_sizes[0] / NIN;
    qcirc_kernel<<<batch, 32>>>(x, theta, alpha_raw, beta_raw,
                                head_w, head_b, logit_scale, out, batch);
}

// round 8
// speedup vs baseline: 2.5378x; 1.0211x over previous
#include <cuda_runtime.h>
#include <math.h>

#define NIN 49

typedef unsigned long long u64;

// ---- f32x2 packed helpers (sm_100+) ----
__device__ __forceinline__ u64 pk2(float lo, float hi) {
    u64 r; asm("mov.b64 %0, {%1,%2};" : "=l"(r) : "f"(lo), "f"(hi)); return r;
}
__device__ __forceinline__ void upk2(float& lo, float& hi, u64 v) {
    asm("mov.b64 {%0,%1}, %2;" : "=f"(lo), "=f"(hi) : "l"(v));
}
__device__ __forceinline__ u64 fma2(u64 a, u64 b, u64 c) {
    u64 d; asm("fma.rn.f32x2 %0, %1, %2, %3;" : "=l"(d) : "l"(a), "l"(b), "l"(c)); return d;
}
__device__ __forceinline__ u64 mul2(u64 a, u64 b) {
    u64 d; asm("mul.rn.f32x2 %0, %1, %2;" : "=l"(d) : "l"(a), "l"(b)); return d;
}

// gray-fold c-index for a 4-bit amp index a = (a3,a2,a1,a0): (a3, a2^a3, a1^a2, a0^a1)
__device__ __forceinline__ constexpr int cidx4(int a) {
    return (((a >> 3) & 1) << 3)
         | ((((a >> 2) ^ (a >> 3)) & 1) << 2)
         | ((((a >> 1) ^ (a >> 2)) & 1) << 1)
         | (((a ^ (a >> 1)) & 1));
}

// Two warps (64 threads) = one sample. Amp index z (10 bits):
//   z9 = warp, z[8:4] = lane, z[3:1] = slot k (8 u64 SoA pairs), z0 = packed half.
// Qubit q acts on bit 9-q:
//   q0 -> warp bit (cross-warp via SMEM), q1..q5 -> lane bits (shfl butterfly),
//   q6..q8 -> slot bits (pure f32x2 FMA), q9 -> packed bit (scalar).
// Layer 0 (product state) is constructed directly with its CNOT permutation folded in.
// The LAST layer's CNOT-chain permutation is folded into the readout weights.
__global__ void __launch_bounds__(64)
qcirc_kernel(const float* __restrict__ x,
             const float* __restrict__ theta,
             const float* __restrict__ alpha_raw,
             const float* __restrict__ beta_raw,
             const float* __restrict__ head_w,
             const float* __restrict__ head_b,
             const float* __restrict__ logit_scale,
             float* __restrict__ out, int batch)
{
    __shared__ u64 xch[16][64];     // [j<8]=re slot j, [8+j]=im slot j; col = thread
    __shared__ float red[2];

    const unsigned FULL = 0xFFFFFFFFu;
    const int t    = threadIdx.x;
    const int lane = t & 31;
    const int w    = t >> 5;
    const int b    = blockIdx.x;
    if (b >= batch) return;

    // ---- per-lane fused gate coefficients (identical in both warps) ----
    // U = RX(theta)*RY(enc) = [[A,-B],[conj(B),conj(A)]]
    // A = cx*cy - i*sx*sy,  B = cx*sy + i*sx*cy
    float myAx, myAy, myBx, myBy;
    {
        const int g  = (lane < 30) ? lane : 0;
        const float th = theta[g];
        const float ar = alpha_raw[g];
        const float br = beta_raw[g];
        const float xv = x[b * NIN + g];
        float sp    = fmaxf(ar, 0.0f) + log1pf(expf(-fabsf(ar)));   // softplus
        float alpha = sp + 1e-6f;
        float beta  = tanhf(br);
        const float HALF_PI = 1.5707963267948966f;                  // 0.5 * pi
        float hy = HALF_PI * (alpha * xv + beta);
        float sy, cy; sincosf(hy, &sy, &cy);
        float sx, cx; sincosf(0.5f * th, &sx, &cx);
        myAx = cx * cy;
        myAy = -sx * sy;
        myBx = cx * sy;
        myBy = sx * cy;
    }

    const int l4 = (lane >> 4) & 1, l3 = (lane >> 3) & 1, l2 = (lane >> 2) & 1,
              l1 = (lane >> 1) & 1, l0 = lane & 1;

    // =====================================================================
    // Layer 0 + its CNOT chain, folded product state:
    //   amp[y] = prod_q f_q(bit_{9-q}(y ^ (y>>1)))
    //   f_q(0) = A_q = (Ax,Ay);  f_q(1) = conj(B_q) = (Bx,-By)
    // qubit bits of y' : q0<-w, q1<-l4^w, q2<-l3^l4, q3<-l2^l3, q4<-l1^l2,
    //   q5<-l0^l1 (all thread-local), q6<-k2^l0 (l0 folded into factor swap),
    //   q7<-k1^k2, q8<-k0^k1, q9<-h^k0 (compile-time c-index renaming)
    // =====================================================================
    u64 srp[8], sip[8];
    {
        // thread factor (qubits 0..5)
        float lfr, lfi;
        {
            const int gb[6] = { w, l4 ^ w, l3 ^ l4, l2 ^ l3, l1 ^ l2, l0 ^ l1 };
            float Ax = __shfl_sync(FULL, myAx, 0);
            float Ay = __shfl_sync(FULL, myAy, 0);
            float Bx = __shfl_sync(FULL, myBx, 0);
            float By = __shfl_sync(FULL, myBy, 0);
            lfr = gb[0] ? Bx : Ax;
            lfi = gb[0] ? -By : Ay;
#pragma unroll
            for (int q = 1; q < 6; q++) {
                Ax = __shfl_sync(FULL, myAx, q);
                Ay = __shfl_sync(FULL, myAy, q);
                Bx = __shfl_sync(FULL, myBx, q);
                By = __shfl_sync(FULL, myBy, q);
                const float fr = gb[q] ? Bx : Ax;
                const float fi = gb[q] ? -By : Ay;
                const float nr = lfr * fr - lfi * fi;
                const float ni = lfr * fi + lfi * fr;
                lfr = nr; lfi = ni;
            }
        }

        // reg-qubit factor pairs (qubits 6..9), j = q-6; qubit 6 gets l0-swap
        float f0r[4], f0i[4], f1r[4], f1i[4];
#pragma unroll
        for (int j = 0; j < 4; j++) {
            const int q = 6 + j;
            const float Ax = __shfl_sync(FULL, myAx, q);
            const float Ay = __shfl_sync(FULL, myAy, q);
            const float Bx = __shfl_sync(FULL, myBx, q);
            const float By = __shfl_sync(FULL, myBy, q);
            if (j == 0) {   // f6'(v) = f6(v ^ l0)
                f0r[j] = l0 ? Bx : Ax;  f0i[j] = l0 ? -By : Ay;
                f1r[j] = l0 ? Ax : Bx;  f1i[j] = l0 ? Ay : -By;
            } else {
                f0r[j] = Ax;  f0i[j] = Ay;
                f1r[j] = Bx;  f1i[j] = -By;
            }
        }

        // doubling tree over c-index (bit3<->q6 .. bit0<->q9), seeded with thread factor
        float gr[16], gi[16];
        gr[0] = lfr; gi[0] = lfi;
#pragma unroll
        for (int p = 0; p < 4; p++) {            // bit position p, factor j = 3-p
            const int j  = 3 - p;
            const int sz = 1 << p;
#pragma unroll
            for (int c = 0; c < 16; c++) {       // only c < sz entries are live
                if (c < sz) {
                    const float orr = gr[c], oii = gi[c];
                    gr[c + sz] = orr * f1r[j] - oii * f1i[j];
                    gi[c + sz] = orr * f1i[j] + oii * f1r[j];
                    gr[c]      = orr * f0r[j] - oii * f0i[j];
                    gi[c]      = orr * f0i[j] + oii * f0r[j];
                }
            }
        }

        // pack into SoA state with compile-time c-index renaming (a = 2k+h)
#pragma unroll
        for (int k = 0; k < 8; k++) {
            srp[k] = pk2(gr[cidx4(2 * k)], gr[cidx4(2 * k + 1)]);
            sip[k] = pk2(gi[cidx4(2 * k)], gi[cidx4(2 * k + 1)]);
        }
    }

    // =====================================================================
    // Layers 1 and 2
    // =====================================================================
#pragma unroll 1
    for (int layer = 1; layer < 3; layer++) {
        const int gbase = layer * 10;

        // ---- qubit 0: cross-warp gate via SMEM exchange ----
        {
            __syncthreads();   // prior readers of xch done
#pragma unroll
            for (int j = 0; j < 8; j++) {
                xch[j][t]     = srp[j];
                xch[j + 8][t] = sip[j];
            }
            __syncthreads();

            const int g  = gbase;        // 10 or 20 (< 32)
            const float Ax = __shfl_sync(FULL, myAx, g);
            const float Ay = __shfl_sync(FULL, myAy, g);
            const float Bx = __shfl_sync(FULL, myBx, g);
            const float By = __shfl_sync(FULL, myBy, g);
            const bool hi = (w != 0);
            const float C1x = Ax;
            const float C1y = hi ? -Ay : Ay;
            const float C2x = hi ?  Bx : -Bx;
            const float C2y = -By;
            const u64 c1x2  = pk2(C1x,  C1x);
            const u64 c1y2  = pk2(C1y,  C1y);
            const u64 nc1y2 = pk2(-C1y, -C1y);
            const u64 c2x2  = pk2(C2x,  C2x);
            const u64 c2y2  = pk2(C2y,  C2y);
            const u64 nc2y2 = pk2(-C2y, -C2y);
            const int pt = t ^ 32;       // partner thread (other warp, same lane)
#pragma unroll
            for (int k = 0; k < 8; k++) {
                const u64 prp = xch[k][pt];
                const u64 pip = xch[k + 8][pt];
                u64 nr = mul2(c1x2, srp[k]);
                nr = fma2(nc1y2, sip[k], nr);
                nr = fma2(c2x2, prp, nr);
                nr = fma2(nc2y2, pip, nr);
                u64 ni = mul2(c1x2, sip[k]);
                ni = fma2(c1y2, srp[k], ni);
                ni = fma2(c2x2, pip, ni);
                ni = fma2(c2y2, prp, ni);
                srp[k] = nr; sip[k] = ni;
            }
        }

        // ---- qubits 1..5: lane-bit gates via shfl.xor butterfly ----
#pragma unroll
        for (int q = 1; q < 6; q++) {
            const int g  = gbase + q;
            const float Ax = __shfl_sync(FULL, myAx, g);
            const float Ay = __shfl_sync(FULL, myAy, g);
            const float Bx = __shfl_sync(FULL, myBx, g);
            const float By = __shfl_sync(FULL, myBy, g);
            const int m = 1 << (5 - q);
            const bool hi = (lane & m) != 0;
            const float C1x = Ax;
            const float C1y = hi ? -Ay : Ay;
            const float C2x = hi ?  Bx : -Bx;
            const float C2y = -By;
            const u64 c1x2  = pk2(C1x,  C1x);
            const u64 c1y2  = pk2(C1y,  C1y);
            const u64 nc1y2 = pk2(-C1y, -C1y);
            const u64 c2x2  = pk2(C2x,  C2x);
            const u64 c2y2  = pk2(C2y,  C2y);
            const u64 nc2y2 = pk2(-C2y, -C2y);
#pragma unroll
            for (int k = 0; k < 8; k++) {
                float r0, r1, i0, i1;
                upk2(r0, r1, srp[k]);
                upk2(i0, i1, sip[k]);
                const float pr0 = __shfl_xor_sync(FULL, r0, m);
                const float pr1 = __shfl_xor_sync(FULL, r1, m);
                const float pi0 = __shfl_xor_sync(FULL, i0, m);
                const float pi1 = __shfl_xor_sync(FULL, i1, m);
                const u64 prp = pk2(pr0, pr1);
                const u64 pip = pk2(pi0, pi1);
                u64 nr = mul2(c1x2, srp[k]);
                nr = fma2(nc1y2, sip[k], nr);
                nr = fma2(c2x2, prp, nr);
                nr = fma2(nc2y2, pip, nr);
                u64 ni = mul2(c1x2, sip[k]);
                ni = fma2(c1y2, srp[k], ni);
                ni = fma2(c2x2, pip, ni);
                ni = fma2(c2y2, prp, ni);
                srp[k] = nr; sip[k] = ni;
            }
        }

        // ---- qubits 6..8: slot-bit gates (pure f32x2 FMA) ----
#pragma unroll
        for (int q = 6; q < 9; q++) {
            const int g  = gbase + q;
            const float Ax = __shfl_sync(FULL, myAx, g);
            const float Ay = __shfl_sync(FULL, myAy, g);
            const float Bx = __shfl_sync(FULL, myBx, g);
            const float By = __shfl_sync(FULL, myBy, g);
            const u64 ax2  = pk2(Ax,  Ax);
            const u64 ay2  = pk2(Ay,  Ay);
            const u64 nay2 = pk2(-Ay, -Ay);
            const u64 bx2  = pk2(Bx,  Bx);
            const u64 nbx2 = pk2(-Bx, -Bx);
            const u64 by2  = pk2(By,  By);
            const u64 nby2 = pk2(-By, -By);
            const int pm = 1 << (8 - q);          // slot bit: 4,2,1
#pragma unroll
            for (int kk = 0; kk < 4; kk++) {
                const int lo = kk & (pm - 1);
                const int p0 = ((kk ^ lo) << 1) | lo;
                const int p1 = p0 | pm;
                const u64 ar = srp[p0], ai = sip[p0];
                const u64 dr = srp[p1], di = sip[p1];
                u64 n0r = mul2(ax2, ar);
                n0r = fma2(nay2, ai, n0r); n0r = fma2(nbx2, dr, n0r); n0r = fma2(by2,  di, n0r);
                u64 n0i = mul2(ax2, ai);
                n0i = fma2(ay2,  ar, n0i); n0i = fma2(nbx2, di, n0i); n0i = fma2(nby2, dr, n0i);
                u64 n1r = mul2(bx2, ar);
                n1r = fma2(by2,  ai, n1r); n1r = fma2(ax2,  dr, n1r); n1r = fma2(ay2,  di, n1r);
                u64 n1i = mul2(bx2, ai);
                n1i = fma2(nby2, ar, n1i); n1i = fma2(ax2,  di, n1i); n1i = fma2(nay2, dr, n1i);
                srp[p0] = n0r; sip[p0] = n0i;
                srp[p1] = n1r; sip[p1] = n1i;
            }
        }

        // ---- qubit 9: intra-register (packed) bit, scalar ----
        {
            const int g  = gbase + 9;
            const float Ax = __shfl_sync(FULL, myAx, g);
            const float Ay = __shfl_sync(FULL, myAy, g);
            const float Bx = __shfl_sync(FULL, myBx, g);
            const float By = __shfl_sync(FULL, myBy, g);
#pragma unroll
            for (int k = 0; k < 8; k++) {
                float ar, dr, ai, di;
                upk2(ar, dr, srp[k]);
                upk2(ai, di, sip[k]);
                const float n0r = Ax*ar - Ay*ai - Bx*dr + By*di;
                const float n0i = Ax*ai + Ay*ar - Bx*di - By*dr;
                const float n1r = Bx*ar + By*ai + Ax*dr + Ay*di;
                const float n1i = Bx*ai - By*ar + Ax*di - Ay*dr;
                srp[k] = pk2(n0r, n1r);
                sip[k] = pk2(n0i, n1i);
            }
        }

        // ---- CNOT chain == gray permutation new[y] = old[y ^ (y>>1)] ----
        // (after layer 1 only; layer 2's permutation folded into readout)
        // src warp = own warp; srcLane = (lane^(lane>>1)) ^ (w<<4);
        // src amp index = cidx4(a) ^ (l0 ? 8 : 0)  (compile-time + parity swap)
        if (layer < 2) {
            float vr[16], vi[16];
#pragma unroll
            for (int k = 0; k < 8; k++) {
                upk2(vr[2*k], vr[2*k+1], srp[k]);
                upk2(vi[2*k], vi[2*k+1], sip[k]);
            }
            const int srcLane = (lane ^ (lane >> 1)) ^ (w << 4);
            const bool hi = (l0 != 0);
#pragma unroll
            for (int j = 0; j < 16; j++) {
                vr[j] = __shfl_sync(FULL, vr[j], srcLane);
                vi[j] = __shfl_sync(FULL, vi[j], srcLane);
            }
#pragma unroll
            for (int k = 0; k < 8; k++) {
                const int c0i = cidx4(2 * k);
                const int c1i = cidx4(2 * k + 1);
                const float f0r = hi ? vr[c0i ^ 8] : vr[c0i];
                const float f0i = hi ? vi[c0i ^ 8] : vi[c0i];
                const float f1r = hi ? vr[c1i ^ 8] : vr[c1i];
                const float f1i = hi ? vi[c1i ^ 8] : vi[c1i];
                srp[k] = pk2(f0r, f1r);
                sip[k] = pk2(f0i, f1i);
            }
        }
    }

    // ---- readout with folded final permutation ----
    // final[y] = S[y^(y>>1)] => sum_y |final[y]|^2 Wz(y) = sum_z |S[z]|^2 Wz(Y(z)),
    // Y_j = z9^...^z_j. Qubit q reads Y_{9-q}.
    const float w0 = head_w[0], w1 = head_w[1], w2 = head_w[2], w3 = head_w[3], w4 = head_w[4];
    const float w5 = head_w[5], w6 = head_w[6], w7 = head_w[7], w8 = head_w[8], w9 = head_w[9];
    const int c0 = w, c1 = c0 ^ l4, c2 = c1 ^ l3, c3 = c2 ^ l2, c4 = c3 ^ l1, c5 = c4 ^ l0;
    const float wl = (c0 ? -w0 : w0) + (c1 ? -w1 : w1) + (c2 ? -w2 : w2)
                   + (c3 ? -w3 : w3) + (c4 ? -w4 : w4) + (c5 ? -w5 : w5);
    const int Plane = c5;   // parity of bits 9..4; flips qubit-6..9 signs globally

    float u = 0.0f, v = 0.0f;
#pragma unroll
    for (int k = 0; k < 8; k++) {
        float r0, r1, i0, i1;
        upk2(r0, r1, srp[k]);
        upk2(i0, i1, sip[k]);
        const float p0 = r0*r0 + i0*i0;
        const float p1 = r1*r1 + i1*i1;
        const int a0 = 2*k, a1 = 2*k + 1;
        // suffix parities of the 4 low bits (k2,k1,k0,h), compile-time per amp
        const int t3_0 = (a0 >> 3) & 1,          t2_0 = t3_0 ^ ((a0 >> 2) & 1),
                  t1_0 = t2_0 ^ ((a0 >> 1) & 1), t0_0 = t1_0 ^ (a0 & 1);
        const int t3_1 = (a1 >> 3) & 1,          t2_1 = t3_1 ^ ((a1 >> 2) & 1),
                  t1_1 = t2_1 ^ ((a1 >> 1) & 1), t0_1 = t1_1 ^ (a1 & 1);
        const float wr0 = (t3_0 ? -w6 : w6) + (t2_0 ? -w7 : w7)
                        + (t1_0 ? -w8 : w8) + (t0_0 ? -w9 : w9);
        const float wr1 = (t3_1 ? -w6 : w6) + (t2_1 ? -w7 : w7)
                        + (t1_1 ? -w8 : w8) + (t0_1 ? -w9 : w9);
        u += p0 + p1;
        v = fmaf(p0, wr0, v);
        v = fmaf(p1, wr1, v);
    }
    float part = fmaf(wl, u, Plane ? -v : v);
#pragma unroll
    for (int o = 16; o > 0; o >>= 1)
        part += __shfl_xor_sync(FULL, part, o);

    if (lane == 0) red[w] = part;
    __syncthreads();
    if (t == 0) {
        const float scale = fminf(fmaxf(logit_scale[0], 0.5f), 80.0f);
        float rr = scale * (red[0] + red[1] + head_b[0]);
        out[b] = fminf(fmaxf(rr, -30.0f), 30.0f);
    }
}

extern "C" void kernel_launch(void* const* d_in, const int* in_sizes, int n_in,
                              void* d_out, int out_size) {
    const float* x           = (const float*)d_in[0];  // (B, 49)
    const float* theta       = (const float*)d_in[1];  // (30,)
    const float* alpha_raw   = (const float*)d_in[2];  // (49,)
    const float* beta_raw    = (const float*)d_in[3];  // (49,)
    const float* head_w      = (const float*)d_in[4];  // (1,10)
    const float* head_b      = (const float*)d_in[5];  // (1,)
    const float* logit_scale = (const float*)d_in[6];  // scalar
    float* out               = (float*)d_out;          // (B,1) float32

    const int batch = in_sizes[0] / NIN;
    qcirc_kernel<<<batch, 64>>>(x, theta, alpha_raw, beta_raw,
                                head_w, head_b, logit_scale, out, batch);
}

// round 9
// speedup vs baseline: 2.6168x; 1.0312x over previous
#include <cuda_runtime.h>
#include <math.h>

#define NIN 49

typedef unsigned long long u64;

// ---- f32x2 packed helpers (sm_100+) ----
__device__ __forceinline__ u64 pk2(float lo, float hi) {
    u64 r; asm("mov.b64 %0, {%1,%2};" : "=l"(r) : "f"(lo), "f"(hi)); return r;
}
__device__ __forceinline__ void upk2(float& lo, float& hi, u64 v) {
    asm("mov.b64 {%0,%1}, %2;" : "=f"(lo), "=f"(hi) : "l"(v));
}
__device__ __forceinline__ u64 fma2(u64 a, u64 b, u64 c) {
    u64 d; asm("fma.rn.f32x2 %0, %1, %2, %3;" : "=l"(d) : "l"(a), "l"(b), "l"(c)); return d;
}
__device__ __forceinline__ u64 mul2(u64 a, u64 b) {
    u64 d; asm("mul.rn.f32x2 %0, %1, %2;" : "=l"(d) : "l"(a), "l"(b)); return d;
}

// gray-fold c-index for a 4-bit amp index a = (a3,a2,a1,a0): (a3, a2^a3, a1^a2, a0^a1)
__device__ __forceinline__ constexpr int cidx4(int a) {
    return (((a >> 3) & 1) << 3)
         | ((((a >> 2) ^ (a >> 3)) & 1) << 2)
         | ((((a >> 1) ^ (a >> 2)) & 1) << 1)
         | (((a ^ (a >> 1)) & 1));
}

// Two warps (64 threads) = one sample. Amp index z (10 bits):
//   z9 = warp, z[8:4] = lane, z[3:1] = slot k (8 u64 SoA pairs), z0 = packed half.
// Qubit q acts on bit 9-q:
//   q0 -> warp bit (cross-warp via SMEM), q1..q5 -> lane bits (shfl butterfly),
//   q6..q8 -> slot bits (pure f32x2 FMA), q9 -> packed bit (vectorized w/ half-swap).
// Layer 0 (product state) is constructed directly with its CNOT permutation folded in.
// The LAST layer's CNOT-chain permutation is folded into the readout weights.
__global__ void __launch_bounds__(64)
qcirc_kernel(const float* __restrict__ x,
             const float* __restrict__ theta,
             const float* __restrict__ alpha_raw,
             const float* __restrict__ beta_raw,
             const float* __restrict__ head_w,
             const float* __restrict__ head_b,
             const float* __restrict__ logit_scale,
             float* __restrict__ out, int batch)
{
    __shared__ u64 xch[16][64];     // [j<8]=re slot j, [8+j]=im slot j; col = thread
    __shared__ float red[2];

    const unsigned FULL = 0xFFFFFFFFu;
    const int t    = threadIdx.x;
    const int lane = t & 31;
    const int w    = t >> 5;
    const int b    = blockIdx.x;
    if (b >= batch) return;

    // ---- per-lane fused gate coefficients (identical in both warps) ----
    // U = RX(theta)*RY(enc) = [[A,-B],[conj(B),conj(A)]]
    // A = cx*cy - i*sx*sy,  B = cx*sy + i*sx*cy
    float myAx, myAy, myBx, myBy;
    {
        const int g  = (lane < 30) ? lane : 0;
        const float th = theta[g];
        const float ar = alpha_raw[g];
        const float br = beta_raw[g];
        const float xv = x[b * NIN + g];
        float sp    = fmaxf(ar, 0.0f) + log1pf(expf(-fabsf(ar)));   // softplus
        float alpha = sp + 1e-6f;
        float beta  = tanhf(br);
        const float HALF_PI = 1.5707963267948966f;                  // 0.5 * pi
        float hy = HALF_PI * (alpha * xv + beta);
        float sy, cy; sincosf(hy, &sy, &cy);
        float sx, cx; sincosf(0.5f * th, &sx, &cx);
        myAx = cx * cy;
        myAy = -sx * sy;
        myBx = cx * sy;
        myBy = sx * cy;
    }

    const int l4 = (lane >> 4) & 1, l3 = (lane >> 3) & 1, l2 = (lane >> 2) & 1,
              l1 = (lane >> 1) & 1, l0 = lane & 1;

    // =====================================================================
    // Layer 0 + its CNOT chain, folded product state:
    //   amp[y] = prod_q f_q(bit_{9-q}(y ^ (y>>1)))
    //   f_q(0) = A_q = (Ax,Ay);  f_q(1) = conj(B_q) = (Bx,-By)
    // qubit bits of y' : q0<-w, q1<-l4^w, q2<-l3^l4, q3<-l2^l3, q4<-l1^l2,
    //   q5<-l0^l1 (all thread-local), q6<-k2^l0 (l0 folded into factor swap),
    //   q7<-k1^k2, q8<-k0^k1, q9<-h^k0 (compile-time c-index renaming)
    // =====================================================================
    u64 srp[8], sip[8];
    {
        // thread factor (qubits 0..5)
        float lfr, lfi;
        {
            const int gb[6] = { w, l4 ^ w, l3 ^ l4, l2 ^ l3, l1 ^ l2, l0 ^ l1 };
            float Ax = __shfl_sync(FULL, myAx, 0);
            float Ay = __shfl_sync(FULL, myAy, 0);
            float Bx = __shfl_sync(FULL, myBx, 0);
            float By = __shfl_sync(FULL, myBy, 0);
            lfr = gb[0] ? Bx : Ax;
            lfi = gb[0] ? -By : Ay;
#pragma unroll
            for (int q = 1; q < 6; q++) {
                Ax = __shfl_sync(FULL, myAx, q);
                Ay = __shfl_sync(FULL, myAy, q);
                Bx = __shfl_sync(FULL, myBx, q);
                By = __shfl_sync(FULL, myBy, q);
                const float fr = gb[q] ? Bx : Ax;
                const float fi = gb[q] ? -By : Ay;
                const float nr = lfr * fr - lfi * fi;
                const float ni = lfr * fi + lfi * fr;
                lfr = nr; lfi = ni;
            }
        }

        // reg-qubit factor pairs (qubits 6..9), j = q-6; qubit 6 gets l0-swap
        float f0r[4], f0i[4], f1r[4], f1i[4];
#pragma unroll
        for (int j = 0; j < 4; j++) {
            const int q = 6 + j;
            const float Ax = __shfl_sync(FULL, myAx, q);
            const float Ay = __shfl_sync(FULL, myAy, q);
            const float Bx = __shfl_sync(FULL, myBx, q);
            const float By = __shfl_sync(FULL, myBy, q);
            if (j == 0) {   // f6'(v) = f6(v ^ l0)
                f0r[j] = l0 ? Bx : Ax;  f0i[j] = l0 ? -By : Ay;
                f1r[j] = l0 ? Ax : Bx;  f1i[j] = l0 ? Ay : -By;
            } else {
                f0r[j] = Ax;  f0i[j] = Ay;
                f1r[j] = Bx;  f1i[j] = -By;
            }
        }

        // doubling tree over c-index (bit3<->q6 .. bit0<->q9), seeded with thread factor
        float gr[16], gi[16];
        gr[0] = lfr; gi[0] = lfi;
#pragma unroll
        for (int p = 0; p < 4; p++) {            // bit position p, factor j = 3-p
            const int j  = 3 - p;
            const int sz = 1 << p;
#pragma unroll
            for (int c = 0; c < 16; c++) {       // only c < sz entries are live
                if (c < sz) {
                    const float orr = gr[c], oii = gi[c];
                    gr[c + sz] = orr * f1r[j] - oii * f1i[j];
                    gi[c + sz] = orr * f1i[j] + oii * f1r[j];
                    gr[c]      = orr * f0r[j] - oii * f0i[j];
                    gi[c]      = orr * f0i[j] + oii * f0r[j];
                }
            }
        }

        // pack into SoA state with compile-time c-index renaming (a = 2k+h)
#pragma unroll
        for (int k = 0; k < 8; k++) {
            srp[k] = pk2(gr[cidx4(2 * k)], gr[cidx4(2 * k + 1)]);
            sip[k] = pk2(gi[cidx4(2 * k)], gi[cidx4(2 * k + 1)]);
        }
    }

    // =====================================================================
    // Layers 1 and 2
    // =====================================================================
#pragma unroll 1
    for (int layer = 1; layer < 3; layer++) {
        const int gbase = layer * 10;

        // ---- qubit 0: cross-warp gate via SMEM exchange ----
        {
            __syncthreads();   // prior readers of xch done
#pragma unroll
            for (int j = 0; j < 8; j++) {
                xch[j][t]     = srp[j];
                xch[j + 8][t] = sip[j];
            }
            __syncthreads();

            const int g  = gbase;        // 10 or 20 (< 32)
            const float Ax = __shfl_sync(FULL, myAx, g);
            const float Ay = __shfl_sync(FULL, myAy, g);
            const float Bx = __shfl_sync(FULL, myBx, g);
            const float By = __shfl_sync(FULL, myBy, g);
            const bool hi = (w != 0);
            const float C1x = Ax;
            const float C1y = hi ? -Ay : Ay;
            const float C2x = hi ?  Bx : -Bx;
            const float C2y = -By;
            const u64 c1x2  = pk2(C1x,  C1x);
            const u64 c1y2  = pk2(C1y,  C1y);
            const u64 nc1y2 = pk2(-C1y, -C1y);
            const u64 c2x2  = pk2(C2x,  C2x);
            const u64 c2y2  = pk2(C2y,  C2y);
            const u64 nc2y2 = pk2(-C2y, -C2y);
            const int pt = t ^ 32;       // partner thread (other warp, same lane)
            // phase 1: batch all partner loads
            u64 prp[8], pip[8];
#pragma unroll
            for (int k = 0; k < 8; k++) {
                prp[k] = xch[k][pt];
                pip[k] = xch[k + 8][pt];
            }
            // phase 2: FMAs
#pragma unroll
            for (int k = 0; k < 8; k++) {
                u64 nr = mul2(c1x2, srp[k]);
                nr = fma2(nc1y2, sip[k], nr);
                nr = fma2(c2x2, prp[k], nr);
                nr = fma2(nc2y2, pip[k], nr);
                u64 ni = mul2(c1x2, sip[k]);
                ni = fma2(c1y2, srp[k], ni);
                ni = fma2(c2x2, pip[k], ni);
                ni = fma2(c2y2, prp[k], ni);
                srp[k] = nr; sip[k] = ni;
            }
        }

        // ---- qubits 1..5: lane-bit gates, two-phase (batch shfl, then FMA) ----
#pragma unroll
        for (int q = 1; q < 6; q++) {
            const int g  = gbase + q;
            const float Ax = __shfl_sync(FULL, myAx, g);
            const float Ay = __shfl_sync(FULL, myAy, g);
            const float Bx = __shfl_sync(FULL, myBx, g);
            const float By = __shfl_sync(FULL, myBy, g);
            const int m = 1 << (5 - q);
            const bool hi = (lane & m) != 0;
            const float C1x = Ax;
            const float C1y = hi ? -Ay : Ay;
            const float C2x = hi ?  Bx : -Bx;
            const float C2y = -By;
            const u64 c1x2  = pk2(C1x,  C1x);
            const u64 c1y2  = pk2(C1y,  C1y);
            const u64 nc1y2 = pk2(-C1y, -C1y);
            const u64 c2x2  = pk2(C2x,  C2x);
            const u64 c2y2  = pk2(C2y,  C2y);
            const u64 nc2y2 = pk2(-C2y, -C2y);
            // phase 1: issue all 32 shuffles back-to-back (MLP over k)
            u64 prp[8], pip[8];
#pragma unroll
            for (int k = 0; k < 8; k++) {
                float r0, r1, i0, i1;
                upk2(r0, r1, srp[k]);
                upk2(i0, i1, sip[k]);
                const float pr0 = __shfl_xor_sync(FULL, r0, m);
                const float pr1 = __shfl_xor_sync(FULL, r1, m);
                const float pi0 = __shfl_xor_sync(FULL, i0, m);
                const float pi1 = __shfl_xor_sync(FULL, i1, m);
                prp[k] = pk2(pr0, pr1);
                pip[k] = pk2(pi0, pi1);
            }
            // phase 2: FMAs
#pragma unroll
            for (int k = 0; k < 8; k++) {
                u64 nr = mul2(c1x2, srp[k]);
                nr = fma2(nc1y2, sip[k], nr);
                nr = fma2(c2x2, prp[k], nr);
                nr = fma2(nc2y2, pip[k], nr);
                u64 ni = mul2(c1x2, sip[k]);
                ni = fma2(c1y2, srp[k], ni);
                ni = fma2(c2x2, pip[k], ni);
                ni = fma2(c2y2, prp[k], ni);
                srp[k] = nr; sip[k] = ni;
            }
        }

        // ---- qubits 6..8: slot-bit gates (pure f32x2 FMA) ----
#pragma unroll
        for (int q = 6; q < 9; q++) {
            const int g  = gbase + q;
            const float Ax = __shfl_sync(FULL, myAx, g);
            const float Ay = __shfl_sync(FULL, myAy, g);
            const float Bx = __shfl_sync(FULL, myBx, g);
            const float By = __shfl_sync(FULL, myBy, g);
            const u64 ax2  = pk2(Ax,  Ax);
            const u64 ay2  = pk2(Ay,  Ay);
            const u64 nay2 = pk2(-Ay, -Ay);
            const u64 bx2  = pk2(Bx,  Bx);
            const u64 nbx2 = pk2(-Bx, -Bx);
            const u64 by2  = pk2(By,  By);
            const u64 nby2 = pk2(-By, -By);
            const int pm = 1 << (8 - q);          // slot bit: 4,2,1
#pragma unroll
            for (int kk = 0; kk < 4; kk++) {
                const int lo = kk & (pm - 1);
                const int p0 = ((kk ^ lo) << 1) | lo;
                const int p1 = p0 | pm;
                const u64 ar = srp[p0], ai = sip[p0];
                const u64 dr = srp[p1], di = sip[p1];
                u64 n0r = mul2(ax2, ar);
                n0r = fma2(nay2, ai, n0r); n0r = fma2(nbx2, dr, n0r); n0r = fma2(by2,  di, n0r);
                u64 n0i = mul2(ax2, ai);
                n0i = fma2(ay2,  ar, n0i); n0i = fma2(nbx2, di, n0i); n0i = fma2(nby2, dr, n0i);
                u64 n1r = mul2(bx2, ar);
                n1r = fma2(by2,  ai, n1r); n1r = fma2(ax2,  dr, n1r); n1r = fma2(ay2,  di, n1r);
                u64 n1i = mul2(bx2, ai);
                n1i = fma2(nby2, ar, n1i); n1i = fma2(ax2,  di, n1i); n1i = fma2(nay2, dr, n1i);
                srp[p0] = n0r; sip[p0] = n0i;
                srp[p1] = n1r; sip[p1] = n1i;
            }
        }

        // ---- qubit 9: intra-register (packed) bit, vectorized via half-swap ----
        // n0r = Ax*ar - Ay*ai - Bx*dr + By*di ; n1r = Bx*ar + By*ai + Ax*dr + Ay*di
        // n0i = Ax*ai + Ay*ar - Bx*di - By*dr ; n1i = Bx*ai - By*ar + Ax*di - Ay*dr
        // As vectors over (half0, half1): with s* = half-swapped state,
        //   n_r = (Ax,Ax)*v_r + (-Ay,Ay)*v_i + (-Bx,Bx)*s_r + (By,By)*s_i
        //   n_i = (Ax,Ax)*v_i + (Ay,-Ay)*v_r + (-Bx,Bx)*s_i + (-By,-By)*s_r
        {
            const int g  = gbase + 9;
            const float Ax = __shfl_sync(FULL, myAx, g);
            const float Ay = __shfl_sync(FULL, myAy, g);
            const float Bx = __shfl_sync(FULL, myBx, g);
            const float By = __shfl_sync(FULL, myBy, g);
            const u64 axx = pk2(Ax,  Ax);
            const u64 ayp = pk2(-Ay, Ay);
            const u64 aym = pk2(Ay, -Ay);
            const u64 bxp = pk2(-Bx, Bx);
            const u64 byp = pk2(By,  By);
            const u64 bym = pk2(-By, -By);
#pragma unroll
            for (int k = 0; k < 8; k++) {
                float ar, dr, ai, di;
                upk2(ar, dr, srp[k]);
                upk2(ai, di, sip[k]);
                const u64 swr = pk2(dr, ar);
                const u64 swi = pk2(di, ai);
                u64 nr = mul2(axx, srp[k]);
                nr = fma2(ayp, sip[k], nr);
                nr = fma2(bxp, swr, nr);
                nr = fma2(byp, swi, nr);
                u64 ni = mul2(axx, sip[k]);
                ni = fma2(aym, srp[k], ni);
                ni = fma2(bxp, swi, ni);
                ni = fma2(bym, swr, ni);
                srp[k] = nr; sip[k] = ni;
            }
        }

        // ---- CNOT chain == gray permutation new[y] = old[y ^ (y>>1)] ----
        // (after layer 1 only; layer 2's permutation folded into readout)
        // src warp = own warp; srcLane = (lane^(lane>>1)) ^ (w<<4);
        // src amp index = cidx4(a) ^ (l0 ? 8 : 0)  (compile-time + parity swap)
        if (layer < 2) {
            float vr[16], vi[16];
#pragma unroll
            for (int k = 0; k < 8; k++) {
                upk2(vr[2*k], vr[2*k+1], srp[k]);
                upk2(vi[2*k], vi[2*k+1], sip[k]);
            }
            const int srcLane = (lane ^ (lane >> 1)) ^ (w << 4);
            const bool hi = (l0 != 0);
#pragma unroll
            for (int j = 0; j < 16; j++) {
                vr[j] = __shfl_sync(FULL, vr[j], srcLane);
                vi[j] = __shfl_sync(FULL, vi[j], srcLane);
            }
#pragma unroll
            for (int k = 0; k < 8; k++) {
                const int c0i = cidx4(2 * k);
                const int c1i = cidx4(2 * k + 1);
                const float f0r = hi ? vr[c0i ^ 8] : vr[c0i];
                const float f0i = hi ? vi[c0i ^ 8] : vi[c0i];
                const float f1r = hi ? vr[c1i ^ 8] : vr[c1i];
                const float f1i = hi ? vi[c1i ^ 8] : vi[c1i];
                srp[k] = pk2(f0r, f1r);
                sip[k] = pk2(f0i, f1i);
            }
        }
    }

    // ---- readout with folded final permutation ----
    // final[y] = S[y^(y>>1)] => sum_y |final[y]|^2 Wz(y) = sum_z |S[z]|^2 Wz(Y(z)),
    // Y_j = z9^...^z_j. Qubit q reads Y_{9-q}.
    const float w0 = head_w[0], w1 = head_w[1], w2 = head_w[2], w3 = head_w[3], w4 = head_w[4];
    const float w5 = head_w[5], w6 = head_w[6], w7 = head_w[7], w8 = head_w[8], w9 = head_w[9];
    const int c0 = w, c1 = c0 ^ l4, c2 = c1 ^ l3, c3 = c2 ^ l2, c4 = c3 ^ l1, c5 = c4 ^ l0;
    const float wl = (c0 ? -w0 : w0) + (c1 ? -w1 : w1) + (c2 ? -w2 : w2)
                   + (c3 ? -w3 : w3) + (c4 ? -w4 : w4) + (c5 ? -w5 : w5);
    const int Plane = c5;   // parity of bits 9..4; flips qubit-6..9 signs globally

    float u = 0.0f, v = 0.0f;
#pragma unroll
    for (int k = 0; k < 8; k++) {
        float r0, r1, i0, i1;
        upk2(r0, r1, srp[k]);
        upk2(i0, i1, sip[k]);
        const float p0 = r0*r0 + i0*i0;
        const float p1 = r1*r1 + i1*i1;
        const int a0 = 2*k, a1 = 2*k + 1;
        // suffix parities of the 4 low bits (k2,k1,k0,h), compile-time per amp
        const int t3_0 = (a0 >> 3) & 1,          t2_0 = t3_0 ^ ((a0 >> 2) & 1),
                  t1_0 = t2_0 ^ ((a0 >> 1) & 1), t0_0 = t1_0 ^ (a0 & 1);
        const int t3_1 = (a1 >> 3) & 1,          t2_1 = t3_1 ^ ((a1 >> 2) & 1),
                  t1_1 = t2_1 ^ ((a1 >> 1) & 1), t0_1 = t1_1 ^ (a1 & 1);
        const float wr0 = (t3_0 ? -w6 : w6) + (t2_0 ? -w7 : w7)
                        + (t1_0 ? -w8 : w8) + (t0_0 ? -w9 : w9);
        const float wr1 = (t3_1 ? -w6 : w6) + (t2_1 ? -w7 : w7)
                        + (t1_1 ? -w8 : w8) + (t0_1 ? -w9 : w9);
        u += p0 + p1;
        v = fmaf(p0, wr0, v);
        v = fmaf(p1, wr1, v);
    }
    float part = fmaf(wl, u, Plane ? -v : v);
#pragma unroll
    for (int o = 16; o > 0; o >>= 1)
        part += __shfl_xor_sync(FULL, part, o);

    if (lane == 0) red[w] = part;
    __syncthreads();
    if (t == 0) {
        const float scale = fminf(fmaxf(logit_scale[0], 0.5f), 80.0f);
        float rr = scale * (red[0] + red[1] + head_b[0]);
        out[b] = fminf(fmaxf(rr, -30.0f), 30.0f);
    }
}

extern "C" void kernel_launch(void* const* d_in, const int* in_sizes, int n_in,
                              void* d_out, int out_size) {
    const float* x           = (const float*)d_in[0];  // (B, 49)
    const float* theta       = (const float*)d_in[1];  // (30,)
    const float* alpha_raw   = (const float*)d_in[2];  // (49,)
    const float* beta_raw    = (const float*)d_in[3];  // (49,)
    const float* head_w      = (const float*)d_in[4];  // (1,10)
    const float* head_b      = (const float*)d_in[5];  // (1,)
    const float* logit_scale = (const float*)d_in[6];  // scalar
    float* out               = (float*)d_out;          // (B,1) float32

    const int batch = in_sizes[0] / NIN;
    qcirc_kernel<<<batch, 64>>>(x, theta, alpha_raw, beta_raw,
                                head_w, head_b, logit_scale, out, batch);
}

// round 11
// speedup vs baseline: 2.8000x; 1.0700x over previous
#include <cuda_runtime.h>
#include <math.h>

#define NIN 49

typedef unsigned long long u64;

// ---- f32x2 packed helpers (sm_100+) ----
__device__ __forceinline__ u64 pk2(float lo, float hi) {
    u64 r; asm("mov.b64 %0, {%1,%2};" : "=l"(r) : "f"(lo), "f"(hi)); return r;
}
__device__ __forceinline__ void upk2(float& lo, float& hi, u64 v) {
    asm("mov.b64 {%0,%1}, %2;" : "=f"(lo), "=f"(hi) : "l"(v));
}
__device__ __forceinline__ u64 fma2(u64 a, u64 b, u64 c) {
    u64 d; asm("fma.rn.f32x2 %0, %1, %2, %3;" : "=l"(d) : "l"(a), "l"(b), "l"(c)); return d;
}
__device__ __forceinline__ u64 mul2(u64 a, u64 b) {
    u64 d; asm("mul.rn.f32x2 %0, %1, %2;" : "=l"(d) : "l"(a), "l"(b)); return d;
}

// gray-fold c-index for a 4-bit amp index a = (a3,a2,a1,a0): (a3, a2^a3, a1^a2, a0^a1)
__device__ __forceinline__ constexpr int cidx4(int a) {
    return (((a >> 3) & 1) << 3)
         | ((((a >> 2) ^ (a >> 3)) & 1) << 2)
         | ((((a >> 1) ^ (a >> 2)) & 1) << 1)
         | (((a ^ (a >> 1)) & 1));
}

// Two warps (64 threads) = one sample. Amp index z (10 bits):
//   z9 = warp, z[8:4] = lane, z[3:1] = slot k (8 u64 SoA pairs), z0 = packed half.
// Qubit q acts on bit 9-q:
//   q0 -> warp bit (cross-warp via SMEM), q1..q5 -> lane bits (shfl butterfly),
//   q6..q8 -> slot bits (pure f32x2 FMA), q9 -> packed bit (vectorized w/ half-swap).
// Layer 0 (product state) is constructed directly with its CNOT permutation folded in.
// Layer 2 uses row-phase gauge: each gate -> [[P,-C],[conj(C),P]] with P real
// (12 FMA per pair instead of 16); the per-row phases are unobservable in |amp|^2.
// The LAST layer's CNOT-chain permutation is folded into the readout weights.
__global__ void __launch_bounds__(64)
qcirc_kernel(const float* __restrict__ x,
             const float* __restrict__ theta,
             const float* __restrict__ alpha_raw,
             const float* __restrict__ beta_raw,
             const float* __restrict__ head_w,
             const float* __restrict__ head_b,
             const float* __restrict__ logit_scale,
             float* __restrict__ out, int batch)
{
    __shared__ u64 xch[16][64];     // [j<8]=re slot j, [8+j]=im slot j; col = thread
    __shared__ float red[2];

    const unsigned FULL = 0xFFFFFFFFu;
    const int t    = threadIdx.x;
    const int lane = t & 31;
    const int w    = t >> 5;
    const int b    = blockIdx.x;
    if (b >= batch) return;

    // ---- per-lane fused gate coefficients (identical in both warps) ----
    // U = RX(theta)*RY(enc) = [[A,-B],[conj(B),conj(A)]]
    // A = cx*cy - i*sx*sy,  B = cx*sy + i*sx*cy
    float myAx, myAy, myBx, myBy;
    float myP, myCx, myCy;          // layer-2 gauge: P=|A|, C = B*conj(A)/|A|
    {
        const int g  = (lane < 30) ? lane : 0;
        const float th = theta[g];
        const float ar = alpha_raw[g];
        const float br = beta_raw[g];
        const float xv = x[b * NIN + g];
        float sp    = fmaxf(ar, 0.0f) + log1pf(expf(-fabsf(ar)));   // softplus
        float alpha = sp + 1e-6f;
        float beta  = tanhf(br);
        const float HALF_PI = 1.5707963267948966f;                  // 0.5 * pi
        float hy = HALF_PI * (alpha * xv + beta);
        float sy, cy; sincosf(hy, &sy, &cy);
        float sx, cx; sincosf(0.5f * th, &sx, &cx);
        myAx = cx * cy;
        myAy = -sx * sy;
        myBx = cx * sy;
        myBy = sx * cy;
        const float nA = fmaxf(myAx * myAx + myAy * myAy, 1e-28f);
        const float ri = rsqrtf(nA);
        myP  = nA * ri;
        myCx = (myBx * myAx + myBy * myAy) * ri;
        myCy = (myBy * myAx - myBx * myAy) * ri;
    }

    const int l4 = (lane >> 4) & 1, l3 = (lane >> 3) & 1, l2 = (lane >> 2) & 1,
              l1 = (lane >> 1) & 1, l0 = lane & 1;

    // =====================================================================
    // Layer 0 + its CNOT chain, folded product state:
    //   amp[y] = prod_q f_q(bit_{9-q}(y ^ (y>>1)))
    //   f_q(0) = A_q = (Ax,Ay);  f_q(1) = conj(B_q) = (Bx,-By)
    // qubit bits of y' : q0<-w, q1<-l4^w, q2<-l3^l4, q3<-l2^l3, q4<-l1^l2,
    //   q5<-l0^l1 (all thread-local), q6<-k2^l0 (l0 folded into factor swap),
    //   q7<-k1^k2, q8<-k0^k1, q9<-h^k0 (compile-time c-index renaming)
    // =====================================================================
    u64 srp[8], sip[8];
    {
        // thread factor (qubits 0..5)
        float lfr, lfi;
        {
            const int gb[6] = { w, l4 ^ w, l3 ^ l4, l2 ^ l3, l1 ^ l2, l0 ^ l1 };
            float Ax = __shfl_sync(FULL, myAx, 0);
            float Ay = __shfl_sync(FULL, myAy, 0);
            float Bx = __shfl_sync(FULL, myBx, 0);
            float By = __shfl_sync(FULL, myBy, 0);
            lfr = gb[0] ? Bx : Ax;
            lfi = gb[0] ? -By : Ay;
#pragma unroll
            for (int q = 1; q < 6; q++) {
                Ax = __shfl_sync(FULL, myAx, q);
                Ay = __shfl_sync(FULL, myAy, q);
                Bx = __shfl_sync(FULL, myBx, q);
                By = __shfl_sync(FULL, myBy, q);
                const float fr = gb[q] ? Bx : Ax;
                const float fi = gb[q] ? -By : Ay;
                const float nr = lfr * fr - lfi * fi;
                const float ni = lfr * fi + lfi * fr;
                lfr = nr; lfi = ni;
            }
        }

        // reg-qubit factor pairs (qubits 6..9), j = q-6; qubit 6 gets l0-swap
        float f0r[4], f0i[4], f1r[4], f1i[4];
#pragma unroll
        for (int j = 0; j < 4; j++) {
            const int q = 6 + j;
            const float Ax = __shfl_sync(FULL, myAx, q);
            const float Ay = __shfl_sync(FULL, myAy, q);
            const float Bx = __shfl_sync(FULL, myBx, q);
            const float By = __shfl_sync(FULL, myBy, q);
            if (j == 0) {   // f6'(v) = f6(v ^ l0)
                f0r[j] = l0 ? Bx : Ax;  f0i[j] = l0 ? -By : Ay;
                f1r[j] = l0 ? Ax : Bx;  f1i[j] = l0 ? Ay : -By;
            } else {
                f0r[j] = Ax;  f0i[j] = Ay;
                f1r[j] = Bx;  f1i[j] = -By;
            }
        }

        // doubling tree over c-index (bit3<->q6 .. bit0<->q9), seeded with thread factor
        float gr[16], gi[16];
        gr[0] = lfr; gi[0] = lfi;
#pragma unroll
        for (int p = 0; p < 4; p++) {            // bit position p, factor j = 3-p
            const int j  = 3 - p;
            const int sz = 1 << p;
#pragma unroll
            for (int c = 0; c < 16; c++) {       // only c < sz entries are live
                if (c < sz) {
                    const float orr = gr[c], oii = gi[c];
                    gr[c + sz] = orr * f1r[j] - oii * f1i[j];
                    gi[c + sz] = orr * f1i[j] + oii * f1r[j];
                    gr[c]      = orr * f0r[j] - oii * f0i[j];
                    gi[c]      = orr * f0i[j] + oii * f0r[j];
                }
            }
        }

        // pack into SoA state with compile-time c-index renaming (a = 2k+h)
#pragma unroll
        for (int k = 0; k < 8; k++) {
            srp[k] = pk2(gr[cidx4(2 * k)], gr[cidx4(2 * k + 1)]);
            sip[k] = pk2(gi[cidx4(2 * k)], gi[cidx4(2 * k + 1)]);
        }
    }

    // =====================================================================
    // Layer 1 (full 16-FMA/pair gates) + mid CNOT permutation
    // =====================================================================
    {
        // ---- qubit 0: cross-warp gate via SMEM exchange ----
        {
            __syncthreads();
#pragma unroll
            for (int j = 0; j < 8; j++) {
                xch[j][t]     = srp[j];
                xch[j + 8][t] = sip[j];
            }
            __syncthreads();

            const float Ax = __shfl_sync(FULL, myAx, 10);
            const float Ay = __shfl_sync(FULL, myAy, 10);
            const float Bx = __shfl_sync(FULL, myBx, 10);
            const float By = __shfl_sync(FULL, myBy, 10);
            const bool hi = (w != 0);
            const float C1x = Ax;
            const float C1y = hi ? -Ay : Ay;
            const float C2x = hi ?  Bx : -Bx;
            const float C2y = -By;
            const u64 c1x2  = pk2(C1x,  C1x);
            const u64 c1y2  = pk2(C1y,  C1y);
            const u64 nc1y2 = pk2(-C1y, -C1y);
            const u64 c2x2  = pk2(C2x,  C2x);
            const u64 c2y2  = pk2(C2y,  C2y);
            const u64 nc2y2 = pk2(-C2y, -C2y);
            const int pt = t ^ 32;
            u64 prp[8], pip[8];
#pragma unroll
            for (int k = 0; k < 8; k++) {
                prp[k] = xch[k][pt];
                pip[k] = xch[k + 8][pt];
            }
#pragma unroll
            for (int k = 0; k < 8; k++) {
                u64 nr = mul2(c1x2, srp[k]);
                nr = fma2(nc1y2, sip[k], nr);
                nr = fma2(c2x2, prp[k], nr);
                nr = fma2(nc2y2, pip[k], nr);
                u64 ni = mul2(c1x2, sip[k]);
                ni = fma2(c1y2, srp[k], ni);
                ni = fma2(c2x2, pip[k], ni);
                ni = fma2(c2y2, prp[k], ni);
                srp[k] = nr; sip[k] = ni;
            }
        }

        // ---- qubits 1..5: lane-bit gates, two-phase ----
#pragma unroll
        for (int q = 1; q < 6; q++) {
            const int g  = 10 + q;
            const float Ax = __shfl_sync(FULL, myAx, g);
            const float Ay = __shfl_sync(FULL, myAy, g);
            const float Bx = __shfl_sync(FULL, myBx, g);
            const float By = __shfl_sync(FULL, myBy, g);
            const int m = 1 << (5 - q);
            const bool hi = (lane & m) != 0;
            const float C1x = Ax;
            const float C1y = hi ? -Ay : Ay;
            const float C2x = hi ?  Bx : -Bx;
            const float C2y = -By;
            const u64 c1x2  = pk2(C1x,  C1x);
            const u64 c1y2  = pk2(C1y,  C1y);
            const u64 nc1y2 = pk2(-C1y, -C1y);
            const u64 c2x2  = pk2(C2x,  C2x);
            const u64 c2y2  = pk2(C2y,  C2y);
            const u64 nc2y2 = pk2(-C2y, -C2y);
            u64 prp[8], pip[8];
#pragma unroll
            for (int k = 0; k < 8; k++) {
                float r0, r1, i0, i1;
                upk2(r0, r1, srp[k]);
                upk2(i0, i1, sip[k]);
                const float pr0 = __shfl_xor_sync(FULL, r0, m);
                const float pr1 = __shfl_xor_sync(FULL, r1, m);
                const float pi0 = __shfl_xor_sync(FULL, i0, m);
                const float pi1 = __shfl_xor_sync(FULL, i1, m);
                prp[k] = pk2(pr0, pr1);
                pip[k] = pk2(pi0, pi1);
            }
#pragma unroll
            for (int k = 0; k < 8; k++) {
                u64 nr = mul2(c1x2, srp[k]);
                nr = fma2(nc1y2, sip[k], nr);
                nr = fma2(c2x2, prp[k], nr);
                nr = fma2(nc2y2, pip[k], nr);
                u64 ni = mul2(c1x2, sip[k]);
                ni = fma2(c1y2, srp[k], ni);
                ni = fma2(c2x2, pip[k], ni);
                ni = fma2(c2y2, prp[k], ni);
                srp[k] = nr; sip[k] = ni;
            }
        }

        // ---- qubits 6..8: slot-bit gates ----
#pragma unroll
        for (int q = 6; q < 9; q++) {
            const int g  = 10 + q;
            const float Ax = __shfl_sync(FULL, myAx, g);
            const float Ay = __shfl_sync(FULL, myAy, g);
            const float Bx = __shfl_sync(FULL, myBx, g);
            const float By = __shfl_sync(FULL, myBy, g);
            const u64 ax2  = pk2(Ax,  Ax);
            const u64 ay2  = pk2(Ay,  Ay);
            const u64 nay2 = pk2(-Ay, -Ay);
            const u64 bx2  = pk2(Bx,  Bx);
            const u64 nbx2 = pk2(-Bx, -Bx);
            const u64 by2  = pk2(By,  By);
            const u64 nby2 = pk2(-By, -By);
            const int pm = 1 << (8 - q);
#pragma unroll
            for (int kk = 0; kk < 4; kk++) {
                const int lo = kk & (pm - 1);
                const int p0 = ((kk ^ lo) << 1) | lo;
                const int p1 = p0 | pm;
                const u64 ar = srp[p0], ai = sip[p0];
                const u64 dr = srp[p1], di = sip[p1];
                u64 n0r = mul2(ax2, ar);
                n0r = fma2(nay2, ai, n0r); n0r = fma2(nbx2, dr, n0r); n0r = fma2(by2,  di, n0r);
                u64 n0i = mul2(ax2, ai);
                n0i = fma2(ay2,  ar, n0i); n0i = fma2(nbx2, di, n0i); n0i = fma2(nby2, dr, n0i);
                u64 n1r = mul2(bx2, ar);
                n1r = fma2(by2,  ai, n1r); n1r = fma2(ax2,  dr, n1r); n1r = fma2(ay2,  di, n1r);
                u64 n1i = mul2(bx2, ai);
                n1i = fma2(nby2, ar, n1i); n1i = fma2(ax2,  di, n1i); n1i = fma2(nay2, dr, n1i);
                srp[p0] = n0r; sip[p0] = n0i;
                srp[p1] = n1r; sip[p1] = n1i;
            }
        }

        // ---- qubit 9: packed bit, vectorized via half-swap ----
        {
            const float Ax = __shfl_sync(FULL, myAx, 19);
            const float Ay = __shfl_sync(FULL, myAy, 19);
            const float Bx = __shfl_sync(FULL, myBx, 19);
            const float By = __shfl_sync(FULL, myBy, 19);
            const u64 axx = pk2(Ax,  Ax);
            const u64 ayp = pk2(-Ay, Ay);
            const u64 aym = pk2(Ay, -Ay);
            const u64 bxp = pk2(-Bx, Bx);
            const u64 byp = pk2(By,  By);
            const u64 bym = pk2(-By, -By);
#pragma unroll
            for (int k = 0; k < 8; k++) {
                float ar, dr, ai, di;
                upk2(ar, dr, srp[k]);
                upk2(ai, di, sip[k]);
                const u64 swr = pk2(dr, ar);
                const u64 swi = pk2(di, ai);
                u64 nr = mul2(axx, srp[k]);
                nr = fma2(ayp, sip[k], nr);
                nr = fma2(bxp, swr, nr);
                nr = fma2(byp, swi, nr);
                u64 ni = mul2(axx, sip[k]);
                ni = fma2(aym, srp[k], ni);
                ni = fma2(bxp, swi, ni);
                ni = fma2(bym, swr, ni);
                srp[k] = nr; sip[k] = ni;
            }
        }

        // ---- mid CNOT chain == gray permutation new[y] = old[y ^ (y>>1)] ----
        {
            float vr[16], vi[16];
#pragma unroll
            for (int k = 0; k < 8; k++) {
                upk2(vr[2*k], vr[2*k+1], srp[k]);
                upk2(vi[2*k], vi[2*k+1], sip[k]);
            }
            const int srcLane = (lane ^ (lane >> 1)) ^ (w << 4);
            const bool hi = (l0 != 0);
#pragma unroll
            for (int j = 0; j < 16; j++) {
                vr[j] = __shfl_sync(FULL, vr[j], srcLane);
                vi[j] = __shfl_sync(FULL, vi[j], srcLane);
            }
#pragma unroll
            for (int k = 0; k < 8; k++) {
                const int c0i = cidx4(2 * k);
                const int c1i = cidx4(2 * k + 1);
                const float f0r = hi ? vr[c0i ^ 8] : vr[c0i];
                const float f0i = hi ? vi[c0i ^ 8] : vi[c0i];
                const float f1r = hi ? vr[c1i ^ 8] : vr[c1i];
                const float f1i = hi ? vi[c1i ^ 8] : vi[c1i];
                srp[k] = pk2(f0r, f1r);
                sip[k] = pk2(f0i, f1i);
            }
        }
    }

    // =====================================================================
    // Layer 2 — gauge form [[P,-C],[conj(C),P]], P real: 12 FMA per pair.
    // Per-row phases are unobservable in the final |amp|^2 readout.
    // =====================================================================
    {
        // ---- qubit 0: cross-warp gate via SMEM exchange ----
        {
            __syncthreads();
#pragma unroll
            for (int j = 0; j < 8; j++) {
                xch[j][t]     = srp[j];
                xch[j + 8][t] = sip[j];
            }
            __syncthreads();

            const float P  = __shfl_sync(FULL, myP,  20);
            const float Cx = __shfl_sync(FULL, myCx, 20);
            const float Cy = __shfl_sync(FULL, myCy, 20);
            const bool hi = (w != 0);
            const float Dx = hi ? Cx : -Cx;
            const u64 p2   = pk2(P,  P);
            const u64 dx2  = pk2(Dx, Dx);
            const u64 cy2  = pk2(Cy, Cy);
            const u64 ncy2 = pk2(-Cy, -Cy);
            const int pt = t ^ 32;
            u64 prp[8], pip[8];
#pragma unroll
            for (int k = 0; k < 8; k++) {
                prp[k] = xch[k][pt];
                pip[k] = xch[k + 8][pt];
            }
#pragma unroll
            for (int k = 0; k < 8; k++) {
                u64 nr = mul2(p2, srp[k]);
                nr = fma2(dx2, prp[k], nr);
                nr = fma2(cy2, pip[k], nr);
                u64 ni = mul2(p2, sip[k]);
                ni = fma2(dx2, pip[k], ni);
                ni = fma2(ncy2, prp[k], ni);
                srp[k] = nr; sip[k] = ni;
            }
        }

        // ---- qubits 1..5: lane-bit gauge gates, two-phase ----
#pragma unroll
        for (int q = 1; q < 6; q++) {
            const int g  = 20 + q;
            const float P  = __shfl_sync(FULL, myP,  g);
            const float Cx = __shfl_sync(FULL, myCx, g);
            const float Cy = __shfl_sync(FULL, myCy, g);
            const int m = 1 << (5 - q);
            const bool hi = (lane & m) != 0;
            const float Dx = hi ? Cx : -Cx;
            const u64 p2   = pk2(P,  P);
            const u64 dx2  = pk2(Dx, Dx);
            const u64 cy2  = pk2(Cy, Cy);
            const u64 ncy2 = pk2(-Cy, -Cy);
            u64 prp[8], pip[8];
#pragma unroll
            for (int k = 0; k < 8; k++) {
                float r0, r1, i0, i1;
                upk2(r0, r1, srp[k]);
                upk2(i0, i1, sip[k]);
                const float pr0 = __shfl_xor_sync(FULL, r0, m);
                const float pr1 = __shfl_xor_sync(FULL, r1, m);
                const float pi0 = __shfl_xor_sync(FULL, i0, m);
                const float pi1 = __shfl_xor_sync(FULL, i1, m);
                prp[k] = pk2(pr0, pr1);
                pip[k] = pk2(pi0, pi1);
            }
#pragma unroll
            for (int k = 0; k < 8; k++) {
                u64 nr = mul2(p2, srp[k]);
                nr = fma2(dx2, prp[k], nr);
                nr = fma2(cy2, pip[k], nr);
                u64 ni = mul2(p2, sip[k]);
                ni = fma2(dx2, pip[k], ni);
                ni = fma2(ncy2, prp[k], ni);
                srp[k] = nr; sip[k] = ni;
            }
        }

        // ---- qubits 6..8: slot-bit gauge gates ----
#pragma unroll
        for (int q = 6; q < 9; q++) {
            const int g  = 20 + q;
            const float P  = __shfl_sync(FULL, myP,  g);
            const float Cx = __shfl_sync(FULL, myCx, g);
            const float Cy = __shfl_sync(FULL, myCy, g);
            const u64 p2   = pk2(P,  P);
            const u64 cx2  = pk2(Cx,  Cx);
            const u64 ncx2 = pk2(-Cx, -Cx);
            const u64 cy2  = pk2(Cy,  Cy);
            const u64 ncy2 = pk2(-Cy, -Cy);
            const int pm = 1 << (8 - q);
#pragma unroll
            for (int kk = 0; kk < 4; kk++) {
                const int lo = kk & (pm - 1);
                const int p0 = ((kk ^ lo) << 1) | lo;
                const int p1 = p0 | pm;
                const u64 ar = srp[p0], ai = sip[p0];
                const u64 dr = srp[p1], di = sip[p1];
                // n0 = P*a - C*d ; n1 = conj(C)*a + P*d
                u64 n0r = mul2(p2, ar);
                n0r = fma2(ncx2, dr, n0r); n0r = fma2(cy2,  di, n0r);
                u64 n0i = mul2(p2, ai);
                n0i = fma2(ncx2, di, n0i); n0i = fma2(ncy2, dr, n0i);
                u64 n1r = mul2(p2, dr);
                n1r = fma2(cx2,  ar, n1r); n1r = fma2(cy2,  ai, n1r);
                u64 n1i = mul2(p2, di);
                n1i = fma2(cx2,  ai, n1i); n1i = fma2(ncy2, ar, n1i);
                srp[p0] = n0r; sip[p0] = n0i;
                srp[p1] = n1r; sip[p1] = n1i;
            }
        }

        // ---- qubit 9: packed bit, gauge, vectorized via half-swap ----
        // n_r = (P,P)*v_r + (-Cx,Cx)*s_r + (Cy,Cy)*s_i
        // n_i = (P,P)*v_i + (-Cx,Cx)*s_i + (-Cy,-Cy)*s_r
        {
            const float P  = __shfl_sync(FULL, myP,  29);
            const float Cx = __shfl_sync(FULL, myCx, 29);
            const float Cy = __shfl_sync(FULL, myCy, 29);
            const u64 p2   = pk2(P,   P);
            const u64 cxp  = pk2(-Cx, Cx);
            const u64 cy2  = pk2(Cy,  Cy);
            const u64 ncy2 = pk2(-Cy, -Cy);
#pragma unroll
            for (int k = 0; k < 8; k++) {
                float ar, dr, ai, di;
                upk2(ar, dr, srp[k]);
                upk2(ai, di, sip[k]);
                const u64 swr = pk2(dr, ar);
                const u64 swi = pk2(di, ai);
                u64 nr = mul2(p2, srp[k]);
                nr = fma2(cxp, swr, nr);
                nr = fma2(cy2, swi, nr);
                u64 ni = mul2(p2, sip[k]);
                ni = fma2(cxp, swi, ni);
                ni = fma2(ncy2, swr, ni);
                srp[k] = nr; sip[k] = ni;
            }
        }
    }

    // ---- readout with folded final permutation ----
    // final[y] = S[y^(y>>1)] => sum_y |final[y]|^2 Wz(y) = sum_z |S[z]|^2 Wz(Y(z)),
    // Y_j = z9^...^z_j. Qubit q reads Y_{9-q}.
    const float w0 = head_w[0], w1 = head_w[1], w2 = head_w[2], w3 = head_w[3], w4 = head_w[4];
    const float w5 = head_w[5], w6 = head_w[6], w7 = head_w[7], w8 = head_w[8], w9 = head_w[9];
    const int c0 = w, c1 = c0 ^ l4, c2 = c1 ^ l3, c3 = c2 ^ l2, c4 = c3 ^ l1, c5 = c4 ^ l0;
    const float wl = (c0 ? -w0 : w0) + (c1 ? -w1 : w1) + (c2 ? -w2 : w2)
                   + (c3 ? -w3 : w3) + (c4 ? -w4 : w4) + (c5 ? -w5 : w5);
    const int Plane = c5;   // parity of bits 9..4; flips qubit-6..9 signs globally

    float u = 0.0f, v = 0.0f;
#pragma unroll
    for (int k = 0; k < 8; k++) {
        float r0, r1, i0, i1;
        upk2(r0, r1, srp[k]);
        upk2(i0, i1, sip[k]);
        const float p0 = r0*r0 + i0*i0;
        const float p1 = r1*r1 + i1*i1;
        const int a0 = 2*k, a1 = 2*k + 1;
        const int t3_0 = (a0 >> 3) & 1,          t2_0 = t3_0 ^ ((a0 >> 2) & 1),
                  t1_0 = t2_0 ^ ((a0 >> 1) & 1), t0_0 = t1_0 ^ (a0 & 1);
        const int t3_1 = (a1 >> 3) & 1,          t2_1 = t3_1 ^ ((a1 >> 2) & 1),
                  t1_1 = t2_1 ^ ((a1 >> 1) & 1), t0_1 = t1_1 ^ (a1 & 1);
        const float wr0 = (t3_0 ? -w6 : w6) + (t2_0 ? -w7 : w7)
                        + (t1_0 ? -w8 : w8) + (t0_0 ? -w9 : w9);
        const float wr1 = (t3_1 ? -w6 : w6) + (t2_1 ? -w7 : w7)
                        + (t1_1 ? -w8 : w8) + (t0_1 ? -w9 : w9);
        u += p0 + p1;
        v = fmaf(p0, wr0, v);
        v = fmaf(p1, wr1, v);
    }
    float part = fmaf(wl, u, Plane ? -v : v);
#pragma unroll
    for (int o = 16; o > 0; o >>= 1)
        part += __shfl_xor_sync(FULL, part, o);

    if (lane == 0) red[w] = part;
    __syncthreads();
    if (t == 0) {
        const float scale = fminf(fmaxf(logit_scale[0], 0.5f), 80.0f);
        float rr = scale * (red[0] + red[1] + head_b[0]);
        out[b] = fminf(fmaxf(rr, -30.0f), 30.0f);
    }
}

extern "C" void kernel_launch(void* const* d_in, const int* in_sizes, int n_in,
                              void* d_out, int out_size) {
    const float* x           = (const float*)d_in[0];  // (B, 49)
    const float* theta       = (const float*)d_in[1];  // (30,)
    const float* alpha_raw   = (const float*)d_in[2];  // (49,)
    const float* beta_raw    = (const float*)d_in[3];  // (49,)
    const float* head_w      = (const float*)d_in[4];  // (1,10)
    const float* head_b      = (const float*)d_in[5];  // (1,)
    const float* logit_scale = (const float*)d_in[6];  // scalar
    float* out               = (float*)d_out;          // (B,1) float32

    const int batch = in_sizes[0] / NIN;
    qcirc_kernel<<<batch, 64>>>(x, theta, alpha_raw, beta_raw,
                                head_w, head_b, logit_scale, out, batch);
}

// round 15
// speedup vs baseline: 2.9066x; 1.0381x over previous
#include <cuda_runtime.h>
#include <math.h>

#define NIN 49

typedef unsigned long long u64;

// ---- f32x2 packed helpers (sm_100+) ----
__device__ __forceinline__ u64 pk2(float lo, float hi) {
    u64 r; asm("mov.b64 %0, {%1,%2};" : "=l"(r) : "f"(lo), "f"(hi)); return r;
}
__device__ __forceinline__ void upk2(float& lo, float& hi, u64 v) {
    asm("mov.b64 {%0,%1}, %2;" : "=f"(lo), "=f"(hi) : "l"(v));
}
__device__ __forceinline__ u64 fma2(u64 a, u64 b, u64 c) {
    u64 d; asm("fma.rn.f32x2 %0, %1, %2, %3;" : "=l"(d) : "l"(a), "l"(b), "l"(c)); return d;
}
__device__ __forceinline__ u64 mul2(u64 a, u64 b) {
    u64 d; asm("mul.rn.f32x2 %0, %1, %2;" : "=l"(d) : "l"(a), "l"(b)); return d;
}

// Two warps (64 threads) = one sample. Amp index z (10 bits):
//   z9 = warp, z[8:4] = lane, z[3:1] = slot k (8 u64 SoA pairs), z0 = packed half.
// Qubit q acts on bit 9-q:
//   q0 -> warp bit (cross-warp via SMEM), q1..q5 -> lane bits (shfl butterfly),
//   q6..q8 -> slot bits (pure f32x2 FMA), q9 -> packed bit (vectorized w/ half-swap).
// Layer 0 (product state) is constructed directly with its CNOT permutation folded in.
// BOTH layers 1 and 2 use the gauge form [[P,-C],[conj(C),P]] with P real (12 FMA/pair):
//   layer 1: RIGHT gauge U' = U*H, H=diag(e^{-i psi},e^{+i psi}), psi=arg(A), C=B*A/|A|.
//     Compensation H^{-1}=diag(e^{+i psi},e^{-i psi}) acts on layer-1's INPUT basis
//     (bits of y, NOT the permuted bits): per-qubit phases c_q(b)=e^{i psi_q (1-2b)}.
//     These are merged EXACTLY into the layer-0 construction: thread part (qubits 0..5,
//     thread-local bits) into the seed; reg part (qubits 6..9) into a doubling tree run
//     directly in amp coordinates with branch-constant combined factors
//     F_j[prev][bit] = f_j(bit^prev) * c_j(bit).
//   layer 2: LEFT gauge diag*U, C = B*conj(A)/|A|; residual per-row phases are
//     unobservable in the final |amp|^2 readout.
// The LAST layer's CNOT-chain permutation is folded into the readout weights.
__global__ void __launch_bounds__(64)
qcirc_kernel(const float* __restrict__ x,
             const float* __restrict__ theta,
             const float* __restrict__ alpha_raw,
             const float* __restrict__ beta_raw,
             const float* __restrict__ head_w,
             const float* __restrict__ head_b,
             const float* __restrict__ logit_scale,
             float* __restrict__ out, int batch)
{
    __shared__ u64 xch[16][64];     // [j<8]=re slot j, [8+j]=im slot j; col = thread
    __shared__ float red[2];

    const unsigned FULL = 0xFFFFFFFFu;
    const int t    = threadIdx.x;
    const int lane = t & 31;
    const int w    = t >> 5;
    const int b    = blockIdx.x;
    if (b >= batch) return;

    // ---- per-lane fused gate coefficients (identical in both warps) ----
    // U = RX(theta)*RY(enc) = [[A,-B],[conj(B),conj(A)]]
    // A = cx*cy - i*sx*sy,  B = cx*sy + i*sx*cy
    float myAx, myAy, myBx, myBy;   // lanes 0..9: layer-0 product factors (pure)
    float myP, myCx, myCy;          // lanes 10..29: gauge coefficients
    float myEx, myEy;               // e^{i psi} = A/|A| (used from lanes 10..19)
    {
        const int g  = (lane < 30) ? lane : 0;
        const float th = theta[g];
        const float ar = alpha_raw[g];
        const float br = beta_raw[g];
        const float xv = x[b * NIN + g];
        float sp    = fmaxf(ar, 0.0f) + log1pf(expf(-fabsf(ar)));   // softplus
        float alpha = sp + 1e-6f;
        float beta  = tanhf(br);
        const float HALF_PI = 1.5707963267948966f;                  // 0.5 * pi
        float hy = HALF_PI * (alpha * xv + beta);
        float sy, cy; sincosf(hy, &sy, &cy);
        float sx, cx; sincosf(0.5f * th, &sx, &cx);
        myAx = cx * cy;
        myAy = -sx * sy;
        myBx = cx * sy;
        myBy = sx * cy;
        const float nA = fmaxf(myAx * myAx + myAy * myAy, 1e-28f);
        const float ri = rsqrtf(nA);
        myP  = nA * ri;
        // C = B * (Ax + i*s*Ay) * ri :  s=+1 (layer-1 lanes, right gauge, uses A)
        //                               s=-1 (layer-2 lanes, left gauge, uses conj A)
        const float s   = (lane >= 10 && lane < 20) ? 1.0f : -1.0f;
        const float sAy = s * myAy;
        myCx = (myBx * myAx - myBy * sAy) * ri;
        myCy = (myBy * myAx + myBx * sAy) * ri;
        myEx = myAx * ri;
        myEy = myAy * ri;
    }

    const int l4 = (lane >> 4) & 1, l3 = (lane >> 3) & 1, l2 = (lane >> 2) & 1,
              l1 = (lane >> 1) & 1, l0 = lane & 1;

    // =====================================================================
    // Layer 0 + its CNOT chain + layer-1 gauge compensation, folded:
    //   amp[y] = comp(y) * prod_q f_q(bit_{9-q}(y ^ (y>>1)))
    //   f_q(0) = (Ax,Ay);  f_q(1) = (Bx,-By);  c_q(b) = e^{i psi_q (1-2b)}
    // permuted bits: q0<-w, q1<-l4^w, q2<-l3^l4, q3<-l2^l3, q4<-l1^l2, q5<-l0^l1,
    //   q6<-k2^l0 (l0 folded into factor swap), q7<-k1^k2, q8<-k0^k1, q9<-h^k0
    // direct bits (compensation): q0<-w, q1<-l4 .. q5<-l0, q6<-k2, q7<-k1,
    //   q8<-k0, q9<-h
    // =====================================================================
    u64 srp[8], sip[8];
    {
        const int gb[6] = { w, l4 ^ w, l3 ^ l4, l2 ^ l3, l1 ^ l2, l0 ^ l1 };
        const int cb[6] = { w, l4, l3, l2, l1, l0 };

        // thread seed (qubits 0..5): gate factor at permuted bit x comp at direct bit
        float lfr, lfi;
        {
            float Ax = __shfl_sync(FULL, myAx, 0);
            float Ay = __shfl_sync(FULL, myAy, 0);
            float Bx = __shfl_sync(FULL, myBx, 0);
            float By = __shfl_sync(FULL, myBy, 0);
            lfr = gb[0] ? Bx : Ax;
            lfi = gb[0] ? -By : Ay;
            float ex = __shfl_sync(FULL, myEx, 10);
            float ey = __shfl_sync(FULL, myEy, 10);
            float cey = cb[0] ? -ey : ey;
            float nr = lfr * ex - lfi * cey;
            float ni = lfr * cey + lfi * ex;
            lfr = nr; lfi = ni;
#pragma unroll
            for (int q = 1; q < 6; q++) {
                Ax = __shfl_sync(FULL, myAx, q);
                Ay = __shfl_sync(FULL, myAy, q);
                Bx = __shfl_sync(FULL, myBx, q);
                By = __shfl_sync(FULL, myBy, q);
                const float fr = gb[q] ? Bx : Ax;
                const float fi = gb[q] ? -By : Ay;
                nr = lfr * fr - lfi * fi;
                ni = lfr * fi + lfi * fr;
                lfr = nr; lfi = ni;
                ex = __shfl_sync(FULL, myEx, 10 + q);
                ey = __shfl_sync(FULL, myEy, 10 + q);
                cey = cb[q] ? -ey : ey;
                nr = lfr * ex - lfi * cey;
                ni = lfr * cey + lfi * ex;
                lfr = nr; lfi = ni;
            }
        }

        // combined reg factors: F[j][pb][bit] = f_{6+j}(bit^pb) * c_{6+j}(bit)
        // j=0 (bit3) has no prev bit: only [0][bit] used (f6 pre-swapped by l0).
        float Fr[4][2][2], Fi[4][2][2];
#pragma unroll
        for (int j = 0; j < 4; j++) {
            const int q = 6 + j;
            const float Ax = __shfl_sync(FULL, myAx, q);
            const float Ay = __shfl_sync(FULL, myAy, q);
            const float Bx = __shfl_sync(FULL, myBx, q);
            const float By = __shfl_sync(FULL, myBy, q);
            float f0r, f0i, f1r, f1i;
            if (j == 0) {   // f6'(v) = f6(v ^ l0)
                f0r = l0 ? Bx : Ax;  f0i = l0 ? -By : Ay;
                f1r = l0 ? Ax : Bx;  f1i = l0 ? Ay : -By;
            } else {
                f0r = Ax;  f0i = Ay;
                f1r = Bx;  f1i = -By;
            }
            const float ex = __shfl_sync(FULL, myEx, 16 + j);
            const float ey = __shfl_sync(FULL, myEy, 16 + j);
            // c(0) = (ex, ey); c(1) = (ex, -ey)
            Fr[j][0][0] = f0r * ex - f0i * ey;   Fi[j][0][0] = f0r * ey + f0i * ex;
            Fr[j][0][1] = f1r * ex + f1i * ey;   Fi[j][0][1] = -f1r * ey + f1i * ex;
            Fr[j][1][0] = f1r * ex - f1i * ey;   Fi[j][1][0] = f1r * ey + f1i * ex;
            Fr[j][1][1] = f0r * ex + f0i * ey;   Fi[j][1][1] = -f0r * ey + f0i * ex;
        }

        // doubling tree in amp coordinates a=(k2,k1,k0,h), top-down bit3->bit0.
        // At level j the gate factor's XOR partner (the previously set bit) is the
        // compile-time branch constant pb.
        float gr[16], gi[16];
        gr[0] = lfr; gi[0] = lfi;
        // bit3 (j=0)
        {
            const float a_ = gr[0], c_ = gi[0];
            gr[8] = a_ * Fr[0][0][1] - c_ * Fi[0][0][1];
            gi[8] = a_ * Fi[0][0][1] + c_ * Fr[0][0][1];
            gr[0] = a_ * Fr[0][0][0] - c_ * Fi[0][0][0];
            gi[0] = a_ * Fi[0][0][0] + c_ * Fr[0][0][0];
        }
        // bit2 (j=1)
#pragma unroll
        for (int c0 = 0; c0 < 16; c0 += 8) {
            const int pb = c0 >> 3;
            const float a_ = gr[c0], c_ = gi[c0];
            gr[c0 + 4] = a_ * Fr[1][pb][1] - c_ * Fi[1][pb][1];
            gi[c0 + 4] = a_ * Fi[1][pb][1] + c_ * Fr[1][pb][1];
            gr[c0]     = a_ * Fr[1][pb][0] - c_ * Fi[1][pb][0];
            gi[c0]     = a_ * Fi[1][pb][0] + c_ * Fr[1][pb][0];
        }
        // bit1 (j=2)
#pragma unroll
        for (int c0 = 0; c0 < 16; c0 += 4) {
            const int pb = (c0 >> 2) & 1;
            const float a_ = gr[c0], c_ = gi[c0];
            gr[c0 + 2] = a_ * Fr[2][pb][1] - c_ * Fi[2][pb][1];
            gi[c0 + 2] = a_ * Fi[2][pb][1] + c_ * Fr[2][pb][1];
            gr[c0]     = a_ * Fr[2][pb][0] - c_ * Fi[2][pb][0];
            gi[c0]     = a_ * Fi[2][pb][0] + c_ * Fr[2][pb][0];
        }
        // bit0 (j=3)
#pragma unroll
        for (int c0 = 0; c0 < 16; c0 += 2) {
            const int pb = (c0 >> 1) & 1;
            const float a_ = gr[c0], c_ = gi[c0];
            gr[c0 + 1] = a_ * Fr[3][pb][1] - c_ * Fi[3][pb][1];
            gi[c0 + 1] = a_ * Fi[3][pb][1] + c_ * Fr[3][pb][1];
            gr[c0]     = a_ * Fr[3][pb][0] - c_ * Fi[3][pb][0];
            gi[c0]     = a_ * Fi[3][pb][0] + c_ * Fr[3][pb][0];
        }

        // pack directly (no renaming: tree already in amp coordinates)
#pragma unroll
        for (int k = 0; k < 8; k++) {
            srp[k] = pk2(gr[2 * k], gr[2 * k + 1]);
            sip[k] = pk2(gi[2 * k], gi[2 * k + 1]);
        }
    }

    // =====================================================================
    // Layers 1 and 2 — identical gauge form [[P,-C],[conj(C),P]], 12 FMA/pair
    // =====================================================================
#pragma unroll 1
    for (int layer = 1; layer < 3; layer++) {
        const int gbase = layer * 10;

        // ---- qubit 0: cross-warp gauge gate via SMEM exchange ----
        {
            __syncthreads();   // prior readers of xch done
#pragma unroll
            for (int j = 0; j < 8; j++) {
                xch[j][t]     = srp[j];
                xch[j + 8][t] = sip[j];
            }
            __syncthreads();

            const float P  = __shfl_sync(FULL, myP,  gbase);
            const float Cx = __shfl_sync(FULL, myCx, gbase);
            const float Cy = __shfl_sync(FULL, myCy, gbase);
            const bool hi = (w != 0);
            const float Dx = hi ? Cx : -Cx;
            const u64 p2   = pk2(P,  P);
            const u64 dx2  = pk2(Dx, Dx);
            const u64 cy2  = pk2(Cy, Cy);
            const u64 ncy2 = pk2(-Cy, -Cy);
            const int pt = t ^ 32;
            u64 prp[8], pip[8];
#pragma unroll
            for (int k = 0; k < 8; k++) {
                prp[k] = xch[k][pt];
                pip[k] = xch[k + 8][pt];
            }
#pragma unroll
            for (int k = 0; k < 8; k++) {
                u64 nr = mul2(p2, srp[k]);
                nr = fma2(dx2, prp[k], nr);
                nr = fma2(cy2, pip[k], nr);
                u64 ni = mul2(p2, sip[k]);
                ni = fma2(dx2, pip[k], ni);
                ni = fma2(ncy2, prp[k], ni);
                srp[k] = nr; sip[k] = ni;
            }
        }

        // ---- qubits 1..5: lane-bit gauge gates, two-phase ----
#pragma unroll
        for (int q = 1; q < 6; q++) {
            const int g  = gbase + q;
            const float P  = __shfl_sync(FULL, myP,  g);
            const float Cx = __shfl_sync(FULL, myCx, g);
            const float Cy = __shfl_sync(FULL, myCy, g);
            const int m = 1 << (5 - q);
            const bool hi = (lane & m) != 0;
            const float Dx = hi ? Cx : -Cx;
            const u64 p2   = pk2(P,  P);
            const u64 dx2  = pk2(Dx, Dx);
            const u64 cy2  = pk2(Cy, Cy);
            const u64 ncy2 = pk2(-Cy, -Cy);
            u64 prp[8], pip[8];
#pragma unroll
            for (int k = 0; k < 8; k++) {
                float r0, r1, i0, i1;
                upk2(r0, r1, srp[k]);
                upk2(i0, i1, sip[k]);
                const float pr0 = __shfl_xor_sync(FULL, r0, m);
                const float pr1 = __shfl_xor_sync(FULL, r1, m);
                const float pi0 = __shfl_xor_sync(FULL, i0, m);
                const float pi1 = __shfl_xor_sync(FULL, i1, m);
                prp[k] = pk2(pr0, pr1);
                pip[k] = pk2(pi0, pi1);
            }
#pragma unroll
            for (int k = 0; k < 8; k++) {
                u64 nr = mul2(p2, srp[k]);
                nr = fma2(dx2, prp[k], nr);
                nr = fma2(cy2, pip[k], nr);
                u64 ni = mul2(p2, sip[k]);
                ni = fma2(dx2, pip[k], ni);
                ni = fma2(ncy2, prp[k], ni);
                srp[k] = nr; sip[k] = ni;
            }
        }

        // ---- qubits 6..8: slot-bit gauge gates ----
#pragma unroll
        for (int q = 6; q < 9; q++) {
            const int g  = gbase + q;
            const float P  = __shfl_sync(FULL, myP,  g);
            const float Cx = __shfl_sync(FULL, myCx, g);
            const float Cy = __shfl_sync(FULL, myCy, g);
            const u64 p2   = pk2(P,  P);
            const u64 cx2  = pk2(Cx,  Cx);
            const u64 ncx2 = pk2(-Cx, -Cx);
            const u64 cy2  = pk2(Cy,  Cy);
            const u64 ncy2 = pk2(-Cy, -Cy);
            const int pm = 1 << (8 - q);          // slot bit: 4,2,1
#pragma unroll
            for (int kk = 0; kk < 4; kk++) {
                const int lo = kk & (pm - 1);
                const int p0 = ((kk ^ lo) << 1) | lo;
                const int p1 = p0 | pm;
                const u64 ar = srp[p0], ai = sip[p0];
                const u64 dr = srp[p1], di = sip[p1];
                // n0 = P*a - C*d ; n1 = conj(C)*a + P*d
                u64 n0r = mul2(p2, ar);
                n0r = fma2(ncx2, dr, n0r); n0r = fma2(cy2,  di, n0r);
                u64 n0i = mul2(p2, ai);
                n0i = fma2(ncx2, di, n0i); n0i = fma2(ncy2, dr, n0i);
                u64 n1r = mul2(p2, dr);
                n1r = fma2(cx2,  ar, n1r); n1r = fma2(cy2,  ai, n1r);
                u64 n1i = mul2(p2, di);
                n1i = fma2(cx2,  ai, n1i); n1i = fma2(ncy2, ar, n1i);
                srp[p0] = n0r; sip[p0] = n0i;
                srp[p1] = n1r; sip[p1] = n1i;
            }
        }

        // ---- qubit 9: packed bit, gauge, vectorized via half-swap ----
        // n_r = (P,P)*v_r + (-Cx,Cx)*s_r + (Cy,Cy)*s_i
        // n_i = (P,P)*v_i + (-Cx,Cx)*s_i + (-Cy,-Cy)*s_r
        {
            const int g  = gbase + 9;
            const float P  = __shfl_sync(FULL, myP,  g);
            const float Cx = __shfl_sync(FULL, myCx, g);
            const float Cy = __shfl_sync(FULL, myCy, g);
            const u64 p2   = pk2(P,   P);
            const u64 cxp  = pk2(-Cx, Cx);
            const u64 cy2  = pk2(Cy,  Cy);
            const u64 ncy2 = pk2(-Cy, -Cy);
#pragma unroll
            for (int k = 0; k < 8; k++) {
                float ar, dr, ai, di;
                upk2(ar, dr, srp[k]);
                upk2(ai, di, sip[k]);
                const u64 swr = pk2(dr, ar);
                const u64 swi = pk2(di, ai);
                u64 nr = mul2(p2, srp[k]);
                nr = fma2(cxp, swr, nr);
                nr = fma2(cy2, swi, nr);
                u64 ni = mul2(p2, sip[k]);
                ni = fma2(cxp, swi, ni);
                ni = fma2(ncy2, swr, ni);
                srp[k] = nr; sip[k] = ni;
            }
        }

        // ---- mid CNOT chain == gray permutation new[y] = old[y ^ (y>>1)] ----
        // (after layer 1 only; layer 2's permutation folded into readout)
        if (layer < 2) {
            float vr[16], vi[16];
#pragma unroll
            for (int k = 0; k < 8; k++) {
                upk2(vr[2*k], vr[2*k+1], srp[k]);
                upk2(vi[2*k], vi[2*k+1], sip[k]);
            }
            const int srcLane = (lane ^ (lane >> 1)) ^ (w << 4);
            const bool hi = (l0 != 0);
#pragma unroll
            for (int j = 0; j < 16; j++) {
                vr[j] = __shfl_sync(FULL, vr[j], srcLane);
                vi[j] = __shfl_sync(FULL, vi[j], srcLane);
            }
#pragma unroll
            for (int k = 0; k < 8; k++) {
                const int a0 = 2 * k, a1 = 2 * k + 1;
                const int c0i = (a0 >> 3) * 8 + ((((a0 >> 2) ^ (a0 >> 3)) & 1) << 2)
                              + ((((a0 >> 1) ^ (a0 >> 2)) & 1) << 1) + ((a0 ^ (a0 >> 1)) & 1);
                const int c1i = (a1 >> 3) * 8 + ((((a1 >> 2) ^ (a1 >> 3)) & 1) << 2)
                              + ((((a1 >> 1) ^ (a1 >> 2)) & 1) << 1) + ((a1 ^ (a1 >> 1)) & 1);
                const float f0r = hi ? vr[c0i ^ 8] : vr[c0i];
                const float f0i = hi ? vi[c0i ^ 8] : vi[c0i];
                const float f1r = hi ? vr[c1i ^ 8] : vr[c1i];
                const float f1i = hi ? vi[c1i ^ 8] : vi[c1i];
                srp[k] = pk2(f0r, f1r);
                sip[k] = pk2(f0i, f1i);
            }
        }
    }

    // ---- readout with folded final permutation ----
    // final[y] = S[y^(y>>1)] => sum_y |final[y]|^2 Wz(y) = sum_z |S[z]|^2 Wz(Y(z)),
    // Y_j = z9^...^z_j. Qubit q reads Y_{9-q}.
    const float w0 = head_w[0], w1 = head_w[1], w2 = head_w[2], w3 = head_w[3], w4 = head_w[4];
    const float w5 = head_w[5], w6 = head_w[6], w7 = head_w[7], w8 = head_w[8], w9 = head_w[9];
    const int c0 = w, c1 = c0 ^ l4, c2 = c1 ^ l3, c3 = c2 ^ l2, c4 = c3 ^ l1, c5 = c4 ^ l0;
    const float wl = (c0 ? -w0 : w0) + (c1 ? -w1 : w1) + (c2 ? -w2 : w2)
                   + (c3 ? -w3 : w3) + (c4 ? -w4 : w4) + (c5 ? -w5 : w5);
    const int Plane = c5;   // parity of bits 9..4; flips qubit-6..9 signs globally

    float u = 0.0f, v = 0.0f;
#pragma unroll
    for (int k = 0; k < 8; k++) {
        float r0, r1, i0, i1;
        upk2(r0, r1, srp[k]);
        upk2(i0, i1, sip[k]);
        const float p0 = r0*r0 + i0*i0;
        const float p1 = r1*r1 + i1*i1;
        const int a0 = 2*k, a1 = 2*k + 1;
        const int t3_0 = (a0 >> 3) & 1,          t2_0 = t3_0 ^ ((a0 >> 2) & 1),
                  t1_0 = t2_0 ^ ((a0 >> 1) & 1), t0_0 = t1_0 ^ (a0 & 1);
        const int t3_1 = (a1 >> 3) & 1,          t2_1 = t3_1 ^ ((a1 >> 2) & 1),
                  t1_1 = t2_1 ^ ((a1 >> 1) & 1), t0_1 = t1_1 ^ (a1 & 1);
        const float wr0 = (t3_0 ? -w6 : w6) + (t2_0 ? -w7 : w7)
                        + (t1_0 ? -w8 : w8) + (t0_0 ? -w9 : w9);
        const float wr1 = (t3_1 ? -w6 : w6) + (t2_1 ? -w7 : w7)
                        + (t1_1 ? -w8 : w8) + (t0_1 ? -w9 : w9);
        u += p0 + p1;
        v = fmaf(p0, wr0, v);
        v = fmaf(p1, wr1, v);
    }
    float part = fmaf(wl, u, Plane ? -v : v);
#pragma unroll
    for (int o = 16; o > 0; o >>= 1)
        part += __shfl_xor_sync(FULL, part, o);

    if (lane == 0) red[w] = part;
    __syncthreads();
    if (t == 0) {
        const float scale = fminf(fmaxf(logit_scale[0], 0.5f), 80.0f);
        float rr = scale * (red[0] + red[1] + head_b[0]);
        out[b] = fminf(fmaxf(rr, -30.0f), 30.0f);
    }
}

extern "C" void kernel_launch(void* const* d_in, const int* in_sizes, int n_in,
                              void* d_out, int out_size) {
    const float* x           = (const float*)d_in[0];  // (B, 49)
    const float* theta       = (const float*)d_in[1];  // (30,)
    const float* alpha_raw   = (const float*)d_in[2];  // (49,)
    const float* beta_raw    = (const float*)d_in[3];  // (49,)
    const float* head_w      = (const float*)d_in[4];  // (1,10)
    const float* head_b      = (const float*)d_in[5];  // (1,)
    const float* logit_scale = (const float*)d_in[6];  // scalar
    float* out               = (float*)d_out;          // (B,1) float32

    const int batch = in_sizes[0] / NIN;
    qcirc_kernel<<<batch, 64>>>(x, theta, alpha_raw, beta_raw,
                                head_w, head_b, logit_scale, out, batch);
}